// round 13
// baseline (speedup 1.0000x reference)
#include <cuda_runtime.h>
#include <cuda_fp16.h>
#include <cstdint>

// Problem constants (fixed shapes)
#define NN   8192
#define EE   524288
#define HH   200
#define NCAT 600
#define NPAD 640
#define KP2  256      // layer-2 K padded (200 -> 256)

// ---------------- static scratch ----------------
__device__ __half g_Ah[(size_t)NN * NN];    // row-major fp16 of x
__device__ __half g_Bh[(size_t)NPAD * NN];  // W1^T fp16 [640][8192] (n-major)
__device__ __half g_h1h[NN * KP2];          // h1 fp16 hi, K-padded (pad cols stay 0)
__device__ __half g_h1l[NN * KP2];          // h1 fp16 lo
__device__ __half g_h2h[NN * KP2];
__device__ __half g_h2l[NN * KP2];
__device__ __half g_hqh[NN * KP2];          // hq fp16 (decode gather)
__device__ __half g_B2h[NPAD * KP2];        // W2cat^T fp16 hi [640][256]
__device__ __half g_B2l[NPAD * KP2];
__device__ __half g_Qh[320 * KP2];          // Q^T fp16 hi [320][256]
__device__ __half g_Ql[320 * KP2];
__device__ float g_Y[(size_t)NN * NCAT];
__device__ float g_h1[NN * HH];
__device__ float g_h2[NN * HH];
__device__ float g_hq[NN * HH];
__device__ int   g_cnt[2 * NN];
__device__ int   g_off[2 * (NN + 1)];
__device__ int   g_cur[2 * NN];
__device__ int   g_srcS[EE];
__device__ int   g_srcR[EE];
__device__ int   g_maskfmt;

__device__ __forceinline__ void split_h(float v, __half& hi, __half& lo) {
    hi = __float2half_rn(v);
    lo = __float2half_rn(v - __half2float(hi));
}

__device__ __forceinline__ uint32_t smem_u32(const void* p) {
    uint32_t a;
    asm("{ .reg .u64 t; cvta.to.shared.u64 t, %1; cvt.u32.u64 %0, t; }" : "=r"(a) : "l"(p));
    return a;
}
__device__ __forceinline__ void cp16(uint32_t dst, const void* src) {
    asm volatile("cp.async.cg.shared.global [%0], [%1], 16;" :: "r"(dst), "l"(src));
}
__device__ __forceinline__ void ldsm4(uint32_t& r0, uint32_t& r1, uint32_t& r2, uint32_t& r3,
                                      uint32_t addr) {
    asm volatile("ldmatrix.sync.aligned.m8n8.x4.shared.b16 {%0,%1,%2,%3}, [%4];"
                 : "=r"(r0), "=r"(r1), "=r"(r2), "=r"(r3) : "r"(addr));
}
__device__ __forceinline__ void mma16816h(float* d, const uint32_t* a, const uint32_t* b) {
    asm volatile(
        "mma.sync.aligned.m16n8k16.row.col.f32.f16.f16.f32 "
        "{%0,%1,%2,%3},{%4,%5,%6,%7},{%8,%9},{%0,%1,%2,%3};\n"
        : "+f"(d[0]), "+f"(d[1]), "+f"(d[2]), "+f"(d[3])
        : "r"(a[0]), "r"(a[1]), "r"(a[2]), "r"(a[3]), "r"(b[0]), "r"(b[1]));
}

// ---------------- converters ----------------
__global__ void k_convA(const float* __restrict__ x, __half* __restrict__ hi) {
    size_t base = ((size_t)blockIdx.x * blockDim.x + threadIdx.x) * 4;
    float4 v = *(const float4*)(x + base);
    __half2 p0; p0.x = __float2half_rn(v.x); p0.y = __float2half_rn(v.y);
    __half2 p1; p1.x = __float2half_rn(v.z); p1.y = __float2half_rn(v.w);
    *(__half2*)(hi + base)     = p0;
    *(__half2*)(hi + base + 2) = p1;
}

// W1^T fp16 with transpose: out[n][k] = w_sel[k][n%200], n in [0,640), zero-pad n>=600
__global__ void k_convB(const float* __restrict__ w0, const float* __restrict__ w1,
                        const float* __restrict__ w2, __half* __restrict__ bh) {
    __shared__ float t[32][33];
    int kt = blockIdx.x;
    int nt = blockIdx.y;
    int tx = threadIdx.x & 31, ty = threadIdx.x >> 5;
#pragma unroll
    for (int i = 0; i < 32; i += 8) {
        int k = kt * 32 + ty + i;
        int n = nt * 32 + tx;
        float v = 0.f;
        if (n < NCAT) {
            const float* w = (n < HH) ? w0 : ((n < 2 * HH) ? w1 : w2);
            v = w[(size_t)k * HH + (n % HH)];
        }
        t[ty + i][tx] = v;
    }
    __syncthreads();
#pragma unroll
    for (int i = 0; i < 32; i += 8) {
        int n = nt * 32 + ty + i;
        int k = kt * 32 + tx;
        bh[(size_t)n * NN + k] = __float2half_rn(t[tx][ty + i]);
    }
}

// W2cat^T fp16 hi/lo
__global__ void k_convW2sp(const float* __restrict__ w0, const float* __restrict__ w1,
                           const float* __restrict__ w2, __half* __restrict__ bh,
                           __half* __restrict__ bl) {
    int idx = blockIdx.x * blockDim.x + threadIdx.x;
    int n = idx >> 8, k = idx & 255;
    float v = 0.f;
    if (n < NCAT && k < HH) {
        const float* w = (n < HH) ? w0 : ((n < 2 * HH) ? w1 : w2);
        v = w[k * HH + (n % HH)];
    }
    __half hi, lo;
    split_h(v, hi, lo);
    bh[idx] = hi;
    bl[idx] = lo;
}

// Q^T fp16 hi/lo
__global__ void k_convQsp(const float* __restrict__ Q, __half* __restrict__ qh,
                          __half* __restrict__ ql) {
    int idx = blockIdx.x * blockDim.x + threadIdx.x;
    int n = idx >> 8, k = idx & 255;
    float v = (n < HH && k < HH) ? Q[k * HH + n] : 0.f;
    __half hi, lo;
    split_h(v, hi, lo);
    qh[idx] = hi;
    ql[idx] = lo;
}

// hq fp32 [NN][200] -> fp16 [NN][256] (pad zero)
__global__ void k_convHq(const float* __restrict__ hq, __half* __restrict__ hqh) {
    int idx = blockIdx.x * blockDim.x + threadIdx.x;
    int row = idx >> 8, col = idx & 255;
    hqh[idx] = __float2half_rn((col < HH) ? hq[row * HH + col] : 0.f);
}

// ---------------- fp16 GEMM (single product): tile 128x160, BK=64, ldmatrix ----------------
#define BKH 72   // 64 + 8 halves padding (LDSM conflict-free)
#define SSTRIDE (BKH * (128 + 160))       // halves per stage
#define GEMM_FP16_SMEM (2 * SSTRIDE * 2)  // bytes (2 stages)

__global__ void __launch_bounds__(256, 2) k_gemm_fp16(
    const __half* __restrict__ Ah, const __half* __restrict__ Bh,
    float* __restrict__ C, int N, int K, int ldc)
{
    extern __shared__ __align__(16) __half sm[];
    const int tid  = threadIdx.x;
    const int lane = tid & 31;
    const int wid  = tid >> 5;
    const int wm   = (wid >> 1) << 5;   // 0,32,64,96
    const int wn   = (wid & 1) * 80;    // 0,80
    const int bm   = blockIdx.y * 128;
    const int bn   = blockIdx.x * 160;

    float acc[2][10][4];
#pragma unroll
    for (int mi = 0; mi < 2; mi++)
#pragma unroll
        for (int ni = 0; ni < 10; ni++)
#pragma unroll
            for (int c = 0; c < 4; c++) acc[mi][ni][c] = 0.f;

    const int ktiles = K >> 6;

    auto sAh = [&](int s) -> __half* { return sm + (size_t)s * SSTRIDE; };
    auto sBh = [&](int s) -> __half* { return sm + (size_t)s * SSTRIDE + 128 * BKH; };

    auto issue_load = [&](int kt) {
        int s = kt & 1;
        int gk = kt << 6;
#pragma unroll
        for (int i = 0; i < 4; i++) {
            int idx = i * 256 + tid;
            int r = idx >> 3, seg = (idx & 7) << 3;
            cp16(smem_u32(sAh(s) + r * BKH + seg), Ah + (size_t)(bm + r) * K + gk + seg);
        }
#pragma unroll
        for (int i = 0; i < 5; i++) {
            int idx = i * 256 + tid;
            int r = idx >> 3, seg = (idx & 7) << 3;
            cp16(smem_u32(sBh(s) + r * BKH + seg), Bh + (size_t)(bn + r) * K + gk + seg);
        }
        asm volatile("cp.async.commit_group;");
    };

    const int aOff = (wm + (lane & 7) + ((lane >> 3) & 1) * 8) * BKH + (lane >> 4) * 8;
    const int bOff = (wn + (lane & 7) + (lane >> 4) * 8) * BKH + ((lane >> 3) & 1) * 8;

    issue_load(0);

    for (int kt = 0; kt < ktiles; kt++) {
        if (kt + 1 < ktiles) {
            issue_load(kt + 1);
            asm volatile("cp.async.wait_group 1;");
        } else {
            asm volatile("cp.async.wait_group 0;");
        }
        __syncthreads();

        const uint32_t aBase = smem_u32(sAh(kt & 1)) + aOff * 2;
        const uint32_t bBase = smem_u32(sBh(kt & 1)) + bOff * 2;

#pragma unroll
        for (int ks = 0; ks < 4; ks++) {
            const int kb2 = (ks << 4) * 2;
            uint32_t af[2][4];
            uint32_t bf[10][2];

#pragma unroll
            for (int mi = 0; mi < 2; mi++)
                ldsm4(af[mi][0], af[mi][1], af[mi][2], af[mi][3],
                      aBase + (mi * 16 * BKH) * 2 + kb2);
#pragma unroll
            for (int p = 0; p < 5; p++)
                ldsm4(bf[2 * p][0], bf[2 * p][1], bf[2 * p + 1][0], bf[2 * p + 1][1],
                      bBase + (p * 16 * BKH) * 2 + kb2);

#pragma unroll
            for (int mi = 0; mi < 2; mi++)
#pragma unroll
                for (int ni = 0; ni < 10; ni++)
                    mma16816h(acc[mi][ni], af[mi], bf[ni]);
        }
        __syncthreads();
    }

#pragma unroll
    for (int mi = 0; mi < 2; mi++) {
#pragma unroll
        for (int ni = 0; ni < 10; ni++) {
            int r = bm + wm + (mi << 4) + (lane >> 2);
            int c = bn + wn + (ni << 3) + ((lane & 3) << 1);
            if (c < N) {
                float2 v0 = make_float2(acc[mi][ni][0], acc[mi][ni][1]);
                float2 v1 = make_float2(acc[mi][ni][2], acc[mi][ni][3]);
                *(float2*)(C + (size_t)r * ldc + c) = v0;
                *(float2*)(C + (size_t)(r + 8) * ldc + c) = v1;
            }
        }
    }
}

// ---------------- fp16 split GEMM (3 products, ~fp32 accurate): tile 128x160, BK=32 ----------------
#define BKH2 40  // 32 + 8 halves padding (LDSM conflict-free: 20-word stride)
#define SSTRIDE2 (BKH2 * (2 * 128 + 2 * 160))
#define GEMM_SP_SMEM (2 * SSTRIDE2 * 2)   // 92160 B -> 2 CTAs/SM

__global__ void __launch_bounds__(256, 2) k_gemm_sp(
    const __half* __restrict__ Ah, const __half* __restrict__ Al,
    const __half* __restrict__ Bh, const __half* __restrict__ Bl,
    float* __restrict__ C, int N, int K, int ldc)
{
    extern __shared__ __align__(16) __half sm[];
    const int tid  = threadIdx.x;
    const int lane = tid & 31;
    const int wid  = tid >> 5;
    const int wm   = (wid >> 1) << 5;
    const int wn   = (wid & 1) * 80;
    const int bm   = blockIdx.y * 128;
    const int bn   = blockIdx.x * 160;

    float acc[2][10][4];
#pragma unroll
    for (int mi = 0; mi < 2; mi++)
#pragma unroll
        for (int ni = 0; ni < 10; ni++)
#pragma unroll
            for (int c = 0; c < 4; c++) acc[mi][ni][c] = 0.f;

    const int ktiles = K >> 5;

    auto sA = [&](int s, int a) -> __half* { return sm + (size_t)s * SSTRIDE2 + a * 128 * BKH2; };
    auto sB = [&](int s, int a) -> __half* { return sm + (size_t)s * SSTRIDE2 + 2 * 128 * BKH2 + a * 160 * BKH2; };

    auto issue_load = [&](int kt) {
        int s = kt & 1;
        int gk = kt << 5;
        const __half* gA[2] = {Ah, Al};
        const __half* gB[2] = {Bh, Bl};
#pragma unroll
        for (int a = 0; a < 2; a++) {
#pragma unroll
            for (int i = 0; i < 2; i++) {           // A: 128 rows x 4 chunks(16B)
                int idx = i * 256 + tid;
                int r = idx >> 2, seg = (idx & 3) << 3;
                cp16(smem_u32(sA(s, a) + r * BKH2 + seg), gA[a] + (size_t)(bm + r) * K + gk + seg);
            }
#pragma unroll
            for (int i = 0; i < 3; i++) {           // B: 160 rows x 4 chunks
                int idx = i * 256 + tid;
                int r = idx >> 2, seg = (idx & 3) << 3;
                if (r < 160)
                    cp16(smem_u32(sB(s, a) + r * BKH2 + seg), gB[a] + (size_t)(bn + r) * K + gk + seg);
            }
        }
        asm volatile("cp.async.commit_group;");
    };

    const int aOff = (wm + (lane & 7) + ((lane >> 3) & 1) * 8) * BKH2 + (lane >> 4) * 8;
    const int bOff = (wn + (lane & 7) + (lane >> 4) * 8) * BKH2 + ((lane >> 3) & 1) * 8;

    issue_load(0);

    for (int kt = 0; kt < ktiles; kt++) {
        if (kt + 1 < ktiles) {
            issue_load(kt + 1);
            asm volatile("cp.async.wait_group 1;");
        } else {
            asm volatile("cp.async.wait_group 0;");
        }
        __syncthreads();

        const uint32_t aBaseH = smem_u32(sA(kt & 1, 0)) + aOff * 2;
        const uint32_t aBaseL = smem_u32(sA(kt & 1, 1)) + aOff * 2;
        const uint32_t bBaseH = smem_u32(sB(kt & 1, 0)) + bOff * 2;
        const uint32_t bBaseL = smem_u32(sB(kt & 1, 1)) + bOff * 2;

#pragma unroll
        for (int ks = 0; ks < 2; ks++) {
            const int kb2 = (ks << 4) * 2;
            uint32_t afh[2][4], afl[2][4];
            uint32_t bfh[10][2], bfl[10][2];

#pragma unroll
            for (int mi = 0; mi < 2; mi++) {
                ldsm4(afh[mi][0], afh[mi][1], afh[mi][2], afh[mi][3],
                      aBaseH + (mi * 16 * BKH2) * 2 + kb2);
                ldsm4(afl[mi][0], afl[mi][1], afl[mi][2], afl[mi][3],
                      aBaseL + (mi * 16 * BKH2) * 2 + kb2);
            }
#pragma unroll
            for (int p = 0; p < 5; p++) {
                ldsm4(bfh[2 * p][0], bfh[2 * p][1], bfh[2 * p + 1][0], bfh[2 * p + 1][1],
                      bBaseH + (p * 16 * BKH2) * 2 + kb2);
                ldsm4(bfl[2 * p][0], bfl[2 * p][1], bfl[2 * p + 1][0], bfl[2 * p + 1][1],
                      bBaseL + (p * 16 * BKH2) * 2 + kb2);
            }

#pragma unroll
            for (int mi = 0; mi < 2; mi++)
#pragma unroll
                for (int ni = 0; ni < 10; ni++) {
                    mma16816h(acc[mi][ni], afh[mi], bfh[ni]);
                    mma16816h(acc[mi][ni], afh[mi], bfl[ni]);
                    mma16816h(acc[mi][ni], afl[mi], bfh[ni]);
                }
        }
        __syncthreads();
    }

#pragma unroll
    for (int mi = 0; mi < 2; mi++) {
#pragma unroll
        for (int ni = 0; ni < 10; ni++) {
            int r = bm + wm + (mi << 4) + (lane >> 2);
            int c = bn + wn + (ni << 3) + ((lane & 3) << 1);
            if (c < N) {
                float2 v0 = make_float2(acc[mi][ni][0], acc[mi][ni][1]);
                float2 v1 = make_float2(acc[mi][ni][2], acc[mi][ni][3]);
                *(float2*)(C + (size_t)r * ldc + c) = v0;
                *(float2*)(C + (size_t)(r + 8) * ldc + c) = v1;
            }
        }
    }
}

// ---------------- mask format detection ----------------
__global__ void k_maskdetect(const unsigned char* __restrict__ m, int* flag) {
    int t = blockIdx.x * blockDim.x + threadIdx.x;
    int any = 0;
    for (int i = t; i < 65536; i += 256 * 64)
        if ((i & 3) != 0 && m[i]) any = 1;
    if (any) atomicExch(flag, 1);
}

// ---------------- CSR build ----------------
__global__ void k_zero_counts(int* cnt, int* flag) {
    int i = blockIdx.x * blockDim.x + threadIdx.x;
    if (i < 2 * NN) cnt[i] = 0;
    if (i == 0) *flag = 0;
}

__global__ void k_hist(const int* __restrict__ es, const int* __restrict__ er, int* cnt) {
    int i = blockIdx.x * blockDim.x + threadIdx.x;
    if (i < EE) {
        atomicAdd(&cnt[es[EE + i]], 1);
    } else if (i < 2 * EE) {
        int j = i - EE;
        atomicAdd(&cnt[NN + er[EE + j]], 1);
    }
}

__global__ void k_scan(const int* __restrict__ cnt, int* __restrict__ off, int* __restrict__ cur) {
    int b = blockIdx.x;
    const int* c = cnt + b * NN;
    int* o = off + b * (NN + 1);
    int* u = cur + b * NN;
    __shared__ int ts[1024];
    int t = threadIdx.x;
    int loc[8];
    int s = 0;
#pragma unroll
    for (int i = 0; i < 8; i++) { loc[i] = s; s += c[t * 8 + i]; }
    ts[t] = s;
    __syncthreads();
    for (int d = 1; d < 1024; d <<= 1) {
        int v = (t >= d) ? ts[t - d] : 0;
        __syncthreads();
        ts[t] += v;
        __syncthreads();
    }
    int base = (t > 0) ? ts[t - 1] : 0;
#pragma unroll
    for (int i = 0; i < 8; i++) {
        int v = base + loc[i];
        o[t * 8 + i] = v;
        u[t * 8 + i] = v;
    }
    if (t == 1023) o[NN] = ts[1023];
}

__global__ void k_fill(const int* __restrict__ es, const int* __restrict__ er,
                       int* cur, int* __restrict__ srcS, int* __restrict__ srcR) {
    int i = blockIdx.x * blockDim.x + threadIdx.x;
    if (i < EE) {
        int d = es[EE + i];
        int p = atomicAdd(&cur[d], 1);
        srcS[p] = es[i];
    } else if (i < 2 * EE) {
        int j = i - EE;
        int d = er[EE + j];
        int p = atomicAdd(&cur[NN + d], 1);
        srcR[p] = er[j];
    }
}

// ---------------- combine (fp32 gathers, MLP=8, fused fp16 hi/lo output) ----------------
__global__ void k_combine(const float* __restrict__ Y, const float* __restrict__ bias,
                          const int* __restrict__ offS, const int* __restrict__ srcS,
                          const int* __restrict__ offR, const int* __restrict__ srcR,
                          float* __restrict__ out, __half* __restrict__ outh,
                          __half* __restrict__ outl, int do_relu)
{
    __shared__ int s_src[256];
    const int n = blockIdx.x;
    const int t = threadIdx.x;

    float acc = 0.f;
    if (t < HH) acc = Y[(size_t)n * NCAT + t] + bias[t];

    {
        int s0 = offS[n], s1 = offS[n + 1];
        for (int base = s0; base < s1; base += 256) {
            int cnt = min(256, s1 - base);
            __syncthreads();
            if (t < cnt) s_src[t] = srcS[base + t];
            __syncthreads();
            if (t < HH) {
#pragma unroll 8
                for (int i = 0; i < cnt; i++)
                    acc += Y[(size_t)s_src[i] * NCAT + HH + t];
            }
        }
    }
    {
        int s0 = offR[n], s1 = offR[n + 1];
        for (int base = s0; base < s1; base += 256) {
            int cnt = min(256, s1 - base);
            __syncthreads();
            if (t < cnt) s_src[t] = srcR[base + t];
            __syncthreads();
            if (t < HH) {
#pragma unroll 8
                for (int i = 0; i < cnt; i++)
                    acc += Y[(size_t)s_src[i] * NCAT + 2 * HH + t];
            }
        }
    }
    if (t < HH) {
        if (do_relu) acc = fmaxf(acc, 0.f);
        out[(size_t)n * HH + t] = acc;
        __half hi, lo;
        split_h(acc, hi, lo);
        outh[n * KP2 + t] = hi;   // pad cols [200,256) remain zero (zero-initialized globals)
        outl[n * KP2 + t] = lo;
    }
}

// ---------------- decoder (fp16 gathers: 1x uint4 per lane per row) ----------------
__global__ void k_decode(const __half* __restrict__ hqh, const __half* __restrict__ h2h,
                         const int* __restrict__ er, const void* __restrict__ maskp,
                         const int* __restrict__ fmt, float* __restrict__ out)
{
    int g = blockIdx.x * blockDim.x + threadIdx.x;
    int e = g >> 5;
    int lane = g & 31;
    if (e >= EE) return;
    int src = er[e];
    int dst = er[EE + e];
    float s = 0.f;
    if (lane < 25) {  // 25 * 8 halves = 200
        const uint4* a = (const uint4*)(hqh + (size_t)src * KP2);
        const uint4* b = (const uint4*)(h2h + (size_t)dst * KP2);
        uint4 va = a[lane], vb = b[lane];
        const __half2* pa = (const __half2*)&va;
        const __half2* pb = (const __half2*)&vb;
#pragma unroll
        for (int j = 0; j < 4; j++) {
            float2 fa = __half22float2(pa[j]);
            float2 fb = __half22float2(pb[j]);
            s = fmaf(fa.x, fb.x, s);
            s = fmaf(fa.y, fb.y, s);
        }
    }
#pragma unroll
    for (int o = 16; o; o >>= 1) s += __shfl_xor_sync(0xffffffffu, s, o);
    if (lane == 0) {
        int mb;
        if (*fmt) mb = ((const unsigned char*)maskp)[e];
        else      mb = ((const int*)maskp)[e];
        out[e] = mb ? (s + 3.5f) : 0.f;
    }
}

// ---------------- launch ----------------
extern "C" void kernel_launch(void* const* d_in, const int* in_sizes, int n_in,
                              void* d_out, int out_size)
{
    // Resolve inputs by element count
    const float *x = 0, *w1s = 0, *w1m = 0, *w1r = 0, *b1 = 0;
    const float *w2s = 0, *w2m = 0, *w2r = 0, *b2 = 0, *Q = 0;
    const int *es = 0, *er = 0;
    const void* mask = 0;
    int nE = 0, nW1 = 0, nB = 0, nS = 0;
    for (int i = 0; i < n_in; i++) {
        int s = in_sizes[i];
        void* p = d_in[i];
        if (s == NN * NN) x = (const float*)p;
        else if (s == 2 * EE) { if (nE == 0) es = (const int*)p; else er = (const int*)p; nE++; }
        else if (s == EE) mask = p;
        else if (s == NN * HH) { if (nW1 == 0) w1s = (const float*)p; else if (nW1 == 1) w1m = (const float*)p; else w1r = (const float*)p; nW1++; }
        else if (s == HH) { if (nB == 0) b1 = (const float*)p; else b2 = (const float*)p; nB++; }
        else if (s == HH * HH) {
            if (nS == 0) w2s = (const float*)p;
            else if (nS == 1) w2m = (const float*)p;
            else if (nS == 2) w2r = (const float*)p;
            else Q = (const float*)p;
            nS++;
        }
    }
    float* out = (float*)d_out;

    float *Y, *h1, *h2, *hq;
    __half *Ah, *Bh, *h1h, *h1l, *h2h, *h2l, *hqh, *B2h, *B2l, *Qh, *Ql;
    int *cnt, *off, *cur, *srcS, *srcR, *mfmt;
    cudaGetSymbolAddress((void**)&Ah,   g_Ah);
    cudaGetSymbolAddress((void**)&Bh,   g_Bh);
    cudaGetSymbolAddress((void**)&h1h,  g_h1h);
    cudaGetSymbolAddress((void**)&h1l,  g_h1l);
    cudaGetSymbolAddress((void**)&h2h,  g_h2h);
    cudaGetSymbolAddress((void**)&h2l,  g_h2l);
    cudaGetSymbolAddress((void**)&hqh,  g_hqh);
    cudaGetSymbolAddress((void**)&B2h,  g_B2h);
    cudaGetSymbolAddress((void**)&B2l,  g_B2l);
    cudaGetSymbolAddress((void**)&Qh,   g_Qh);
    cudaGetSymbolAddress((void**)&Ql,   g_Ql);
    cudaGetSymbolAddress((void**)&Y,    g_Y);
    cudaGetSymbolAddress((void**)&h1,   g_h1);
    cudaGetSymbolAddress((void**)&h2,   g_h2);
    cudaGetSymbolAddress((void**)&hq,   g_hq);
    cudaGetSymbolAddress((void**)&cnt,  g_cnt);
    cudaGetSymbolAddress((void**)&off,  g_off);
    cudaGetSymbolAddress((void**)&cur,  g_cur);
    cudaGetSymbolAddress((void**)&srcS, g_srcS);
    cudaGetSymbolAddress((void**)&srcR, g_srcR);
    cudaGetSymbolAddress((void**)&mfmt, g_maskfmt);

    cudaFuncSetAttribute(k_gemm_fp16, cudaFuncAttributeMaxDynamicSharedMemorySize, GEMM_FP16_SMEM);
    cudaFuncSetAttribute(k_gemm_sp,   cudaFuncAttributeMaxDynamicSharedMemorySize, GEMM_SP_SMEM);

    const int* offS = off;
    const int* offR = off + (NN + 1);

    // order: big GEMM at launch index 3 for ncu sampling
    k_convA<<<(size_t)NN * NN / 4 / 256, 256>>>(x, Ah);                       // 0
    k_convB<<<dim3(NN / 32, NPAD / 32), 256>>>(w1s, w1m, w1r, Bh);            // 1
    k_zero_counts<<<(2 * NN + 255) / 256, 256>>>(cnt, mfmt);                  // 2
    k_gemm_fp16<<<dim3(NPAD / 160, NN / 128), 256, GEMM_FP16_SMEM>>>(Ah, Bh, Y, NCAT, NN, NCAT); // 3
    k_maskdetect<<<64, 256>>>((const unsigned char*)mask, mfmt);
    k_hist<<<(2 * EE + 255) / 256, 256>>>(es, er, cnt);
    k_scan<<<2, 1024>>>(cnt, off, cur);
    k_fill<<<(2 * EE + 255) / 256, 256>>>(es, er, cur, srcS, srcR);
    k_combine<<<NN, 256>>>(Y, b1, offS, srcS, offR, srcR, h1, h1h, h1l, 1);

    // layer 2 via split fp16 GEMM (3-product, ~fp32 accurate; K padded to 256)
    k_convW2sp<<<NPAD, 256>>>(w2s, w2m, w2r, B2h, B2l);
    k_gemm_sp<<<dim3(NPAD / 160, NN / 128), 256, GEMM_SP_SMEM>>>(h1h, h1l, B2h, B2l, Y, NCAT, KP2, NCAT);
    k_combine<<<NN, 256>>>(Y, b2, offS, srcS, offR, srcR, h2, h2h, h2l, 0);

    // decoder: hq = h2 @ Q via split fp16 GEMM, then per-edge fp16 dot
    k_convQsp<<<320, 256>>>(Q, Qh, Ql);
    k_gemm_sp<<<dim3(2, NN / 128), 256, GEMM_SP_SMEM>>>(h2h, h2l, Qh, Ql, hq, HH, KP2, HH);
    k_convHq<<<NN, 256>>>(hq, hqh);
    k_decode<<<EE / 8, 256>>>(hqh, h2h, er, mask, mfmt, out);
}

// round 14
// speedup vs baseline: 1.0154x; 1.0154x over previous
#include <cuda_runtime.h>
#include <cuda_fp16.h>
#include <cstdint>

// Problem constants (fixed shapes)
#define NN   8192
#define EE   524288
#define HH   200
#define NCAT 600
#define NPAD 640
#define KP2  256      // layer-2 K padded (200 -> 256)

// ---------------- static scratch ----------------
__device__ __half g_Ah[(size_t)NN * NN];    // row-major fp16 of x
__device__ __half g_Bh[(size_t)NPAD * NN];  // W1^T fp16 [640][8192] (n-major)
__device__ __half g_h1h[NN * KP2];          // h1 fp16 hi, K-padded (pad cols stay 0)
__device__ __half g_h1l[NN * KP2];          // h1 fp16 lo
__device__ __half g_h2h[NN * KP2];
__device__ __half g_h2l[NN * KP2];
__device__ __half g_B2h[NPAD * KP2];        // W2cat^T fp16 hi [640][256]
__device__ __half g_B2l[NPAD * KP2];
__device__ __half g_Qh[320 * KP2];          // Q^T fp16 hi [320][256]
__device__ __half g_Ql[320 * KP2];
__device__ float g_Y[(size_t)NN * NCAT];
__device__ float g_h1[NN * HH];
__device__ float g_h2[NN * HH];
__device__ float g_hq[NN * HH];
__device__ int   g_cnt[2 * NN];
__device__ int   g_off[2 * (NN + 1)];
__device__ int   g_cur[2 * NN];
__device__ int   g_srcS[EE];
__device__ int   g_srcR[EE];
__device__ int   g_maskfmt;

__device__ __forceinline__ void split_h(float v, __half& hi, __half& lo) {
    hi = __float2half_rn(v);
    lo = __float2half_rn(v - __half2float(hi));
}

__device__ __forceinline__ uint32_t smem_u32(const void* p) {
    uint32_t a;
    asm("{ .reg .u64 t; cvta.to.shared.u64 t, %1; cvt.u32.u64 %0, t; }" : "=r"(a) : "l"(p));
    return a;
}
__device__ __forceinline__ void cp16(uint32_t dst, const void* src) {
    asm volatile("cp.async.cg.shared.global [%0], [%1], 16;" :: "r"(dst), "l"(src));
}
__device__ __forceinline__ void ldsm4(uint32_t& r0, uint32_t& r1, uint32_t& r2, uint32_t& r3,
                                      uint32_t addr) {
    asm volatile("ldmatrix.sync.aligned.m8n8.x4.shared.b16 {%0,%1,%2,%3}, [%4];"
                 : "=r"(r0), "=r"(r1), "=r"(r2), "=r"(r3) : "r"(addr));
}
__device__ __forceinline__ void mma16816h(float* d, const uint32_t* a, const uint32_t* b) {
    asm volatile(
        "mma.sync.aligned.m16n8k16.row.col.f32.f16.f16.f32 "
        "{%0,%1,%2,%3},{%4,%5,%6,%7},{%8,%9},{%0,%1,%2,%3};\n"
        : "+f"(d[0]), "+f"(d[1]), "+f"(d[2]), "+f"(d[3])
        : "r"(a[0]), "r"(a[1]), "r"(a[2]), "r"(a[3]), "r"(b[0]), "r"(b[1]));
}

// ---------------- converters ----------------
__global__ void k_convA(const float* __restrict__ x, __half* __restrict__ hi) {
    size_t base = ((size_t)blockIdx.x * blockDim.x + threadIdx.x) * 4;
    float4 v = *(const float4*)(x + base);
    __half2 p0; p0.x = __float2half_rn(v.x); p0.y = __float2half_rn(v.y);
    __half2 p1; p1.x = __float2half_rn(v.z); p1.y = __float2half_rn(v.w);
    *(__half2*)(hi + base)     = p0;
    *(__half2*)(hi + base + 2) = p1;
}

// W1^T fp16 with transpose: out[n][k] = w_sel[k][n%200], n in [0,640), zero-pad n>=600
__global__ void k_convB(const float* __restrict__ w0, const float* __restrict__ w1,
                        const float* __restrict__ w2, __half* __restrict__ bh) {
    __shared__ float t[32][33];
    int kt = blockIdx.x;
    int nt = blockIdx.y;
    int tx = threadIdx.x & 31, ty = threadIdx.x >> 5;
#pragma unroll
    for (int i = 0; i < 32; i += 8) {
        int k = kt * 32 + ty + i;
        int n = nt * 32 + tx;
        float v = 0.f;
        if (n < NCAT) {
            const float* w = (n < HH) ? w0 : ((n < 2 * HH) ? w1 : w2);
            v = w[(size_t)k * HH + (n % HH)];
        }
        t[ty + i][tx] = v;
    }
    __syncthreads();
#pragma unroll
    for (int i = 0; i < 32; i += 8) {
        int n = nt * 32 + ty + i;
        int k = kt * 32 + tx;
        bh[(size_t)n * NN + k] = __float2half_rn(t[tx][ty + i]);
    }
}

// W2cat^T fp16 hi/lo
__global__ void k_convW2sp(const float* __restrict__ w0, const float* __restrict__ w1,
                           const float* __restrict__ w2, __half* __restrict__ bh,
                           __half* __restrict__ bl) {
    int idx = blockIdx.x * blockDim.x + threadIdx.x;
    int n = idx >> 8, k = idx & 255;
    float v = 0.f;
    if (n < NCAT && k < HH) {
        const float* w = (n < HH) ? w0 : ((n < 2 * HH) ? w1 : w2);
        v = w[k * HH + (n % HH)];
    }
    __half hi, lo;
    split_h(v, hi, lo);
    bh[idx] = hi;
    bl[idx] = lo;
}

// Q^T fp16 hi/lo
__global__ void k_convQsp(const float* __restrict__ Q, __half* __restrict__ qh,
                          __half* __restrict__ ql) {
    int idx = blockIdx.x * blockDim.x + threadIdx.x;
    int n = idx >> 8, k = idx & 255;
    float v = (n < HH && k < HH) ? Q[k * HH + n] : 0.f;
    __half hi, lo;
    split_h(v, hi, lo);
    qh[idx] = hi;
    ql[idx] = lo;
}

// ---------------- fp16 GEMM (single product): tile 128x160, BK=64, ldmatrix ----------------
#define BKH 72   // 64 + 8 halves padding (LDSM conflict-free)
#define SSTRIDE (BKH * (128 + 160))       // halves per stage
#define GEMM_FP16_SMEM (2 * SSTRIDE * 2)  // bytes (2 stages)

__global__ void __launch_bounds__(256, 2) k_gemm_fp16(
    const __half* __restrict__ Ah, const __half* __restrict__ Bh,
    float* __restrict__ C, int N, int K, int ldc)
{
    extern __shared__ __align__(16) __half sm[];
    const int tid  = threadIdx.x;
    const int lane = tid & 31;
    const int wid  = tid >> 5;
    const int wm   = (wid >> 1) << 5;   // 0,32,64,96
    const int wn   = (wid & 1) * 80;    // 0,80
    const int bm   = blockIdx.y * 128;
    const int bn   = blockIdx.x * 160;

    float acc[2][10][4];
#pragma unroll
    for (int mi = 0; mi < 2; mi++)
#pragma unroll
        for (int ni = 0; ni < 10; ni++)
#pragma unroll
            for (int c = 0; c < 4; c++) acc[mi][ni][c] = 0.f;

    const int ktiles = K >> 6;

    auto sAh = [&](int s) -> __half* { return sm + (size_t)s * SSTRIDE; };
    auto sBh = [&](int s) -> __half* { return sm + (size_t)s * SSTRIDE + 128 * BKH; };

    auto issue_load = [&](int kt) {
        int s = kt & 1;
        int gk = kt << 6;
#pragma unroll
        for (int i = 0; i < 4; i++) {
            int idx = i * 256 + tid;
            int r = idx >> 3, seg = (idx & 7) << 3;
            cp16(smem_u32(sAh(s) + r * BKH + seg), Ah + (size_t)(bm + r) * K + gk + seg);
        }
#pragma unroll
        for (int i = 0; i < 5; i++) {
            int idx = i * 256 + tid;
            int r = idx >> 3, seg = (idx & 7) << 3;
            cp16(smem_u32(sBh(s) + r * BKH + seg), Bh + (size_t)(bn + r) * K + gk + seg);
        }
        asm volatile("cp.async.commit_group;");
    };

    const int aOff = (wm + (lane & 7) + ((lane >> 3) & 1) * 8) * BKH + (lane >> 4) * 8;
    const int bOff = (wn + (lane & 7) + (lane >> 4) * 8) * BKH + ((lane >> 3) & 1) * 8;

    issue_load(0);

    for (int kt = 0; kt < ktiles; kt++) {
        if (kt + 1 < ktiles) {
            issue_load(kt + 1);
            asm volatile("cp.async.wait_group 1;");
        } else {
            asm volatile("cp.async.wait_group 0;");
        }
        __syncthreads();

        const uint32_t aBase = smem_u32(sAh(kt & 1)) + aOff * 2;
        const uint32_t bBase = smem_u32(sBh(kt & 1)) + bOff * 2;

#pragma unroll
        for (int ks = 0; ks < 4; ks++) {
            const int kb2 = (ks << 4) * 2;
            uint32_t af[2][4];
            uint32_t bf[10][2];

#pragma unroll
            for (int mi = 0; mi < 2; mi++)
                ldsm4(af[mi][0], af[mi][1], af[mi][2], af[mi][3],
                      aBase + (mi * 16 * BKH) * 2 + kb2);
#pragma unroll
            for (int p = 0; p < 5; p++)
                ldsm4(bf[2 * p][0], bf[2 * p][1], bf[2 * p + 1][0], bf[2 * p + 1][1],
                      bBase + (p * 16 * BKH) * 2 + kb2);

#pragma unroll
            for (int mi = 0; mi < 2; mi++)
#pragma unroll
                for (int ni = 0; ni < 10; ni++)
                    mma16816h(acc[mi][ni], af[mi], bf[ni]);
        }
        __syncthreads();
    }

#pragma unroll
    for (int mi = 0; mi < 2; mi++) {
#pragma unroll
        for (int ni = 0; ni < 10; ni++) {
            int r = bm + wm + (mi << 4) + (lane >> 2);
            int c = bn + wn + (ni << 3) + ((lane & 3) << 1);
            if (c < N) {
                float2 v0 = make_float2(acc[mi][ni][0], acc[mi][ni][1]);
                float2 v1 = make_float2(acc[mi][ni][2], acc[mi][ni][3]);
                *(float2*)(C + (size_t)r * ldc + c) = v0;
                *(float2*)(C + (size_t)(r + 8) * ldc + c) = v1;
            }
        }
    }
}

// ---------------- fp16 split GEMM (3 products, ~fp32 accurate): tile 128x160, BK=64 ----------------
#define SSTRIDE2 (BKH * (2 * 128 + 2 * 160))
#define GEMM_SP_SMEM (2 * SSTRIDE2 * 2)   // 1 CTA/SM

__global__ void __launch_bounds__(256, 1) k_gemm_sp(
    const __half* __restrict__ Ah, const __half* __restrict__ Al,
    const __half* __restrict__ Bh, const __half* __restrict__ Bl,
    float* __restrict__ C, int N, int K, int ldc)
{
    extern __shared__ __align__(16) __half sm[];
    const int tid  = threadIdx.x;
    const int lane = tid & 31;
    const int wid  = tid >> 5;
    const int wm   = (wid >> 1) << 5;
    const int wn   = (wid & 1) * 80;
    const int bm   = blockIdx.y * 128;
    const int bn   = blockIdx.x * 160;

    float acc[2][10][4];
#pragma unroll
    for (int mi = 0; mi < 2; mi++)
#pragma unroll
        for (int ni = 0; ni < 10; ni++)
#pragma unroll
            for (int c = 0; c < 4; c++) acc[mi][ni][c] = 0.f;

    const int ktiles = K >> 6;

    auto sA = [&](int s, int a) -> __half* { return sm + (size_t)s * SSTRIDE2 + a * 128 * BKH; };
    auto sB = [&](int s, int a) -> __half* { return sm + (size_t)s * SSTRIDE2 + 2 * 128 * BKH + a * 160 * BKH; };

    auto issue_load = [&](int kt) {
        int s = kt & 1;
        int gk = kt << 6;
        const __half* gA[2] = {Ah, Al};
        const __half* gB[2] = {Bh, Bl};
#pragma unroll
        for (int a = 0; a < 2; a++) {
#pragma unroll
            for (int i = 0; i < 4; i++) {
                int idx = i * 256 + tid;
                int r = idx >> 3, seg = (idx & 7) << 3;
                cp16(smem_u32(sA(s, a) + r * BKH + seg), gA[a] + (size_t)(bm + r) * K + gk + seg);
            }
#pragma unroll
            for (int i = 0; i < 5; i++) {
                int idx = i * 256 + tid;
                int r = idx >> 3, seg = (idx & 7) << 3;
                cp16(smem_u32(sB(s, a) + r * BKH + seg), gB[a] + (size_t)(bn + r) * K + gk + seg);
            }
        }
        asm volatile("cp.async.commit_group;");
    };

    const int aOff = (wm + (lane & 7) + ((lane >> 3) & 1) * 8) * BKH + (lane >> 4) * 8;
    const int bOff = (wn + (lane & 7) + (lane >> 4) * 8) * BKH + ((lane >> 3) & 1) * 8;

    issue_load(0);

    for (int kt = 0; kt < ktiles; kt++) {
        if (kt + 1 < ktiles) {
            issue_load(kt + 1);
            asm volatile("cp.async.wait_group 1;");
        } else {
            asm volatile("cp.async.wait_group 0;");
        }
        __syncthreads();

        const uint32_t aBaseH = smem_u32(sA(kt & 1, 0)) + aOff * 2;
        const uint32_t aBaseL = smem_u32(sA(kt & 1, 1)) + aOff * 2;
        const uint32_t bBaseH = smem_u32(sB(kt & 1, 0)) + bOff * 2;
        const uint32_t bBaseL = smem_u32(sB(kt & 1, 1)) + bOff * 2;

#pragma unroll
        for (int ks = 0; ks < 4; ks++) {
            const int kb2 = (ks << 4) * 2;
            uint32_t afh[2][4], afl[2][4];
            uint32_t bfh[10][2], bfl[10][2];

#pragma unroll
            for (int mi = 0; mi < 2; mi++) {
                ldsm4(afh[mi][0], afh[mi][1], afh[mi][2], afh[mi][3],
                      aBaseH + (mi * 16 * BKH) * 2 + kb2);
                ldsm4(afl[mi][0], afl[mi][1], afl[mi][2], afl[mi][3],
                      aBaseL + (mi * 16 * BKH) * 2 + kb2);
            }
#pragma unroll
            for (int p = 0; p < 5; p++) {
                ldsm4(bfh[2 * p][0], bfh[2 * p][1], bfh[2 * p + 1][0], bfh[2 * p + 1][1],
                      bBaseH + (p * 16 * BKH) * 2 + kb2);
                ldsm4(bfl[2 * p][0], bfl[2 * p][1], bfl[2 * p + 1][0], bfl[2 * p + 1][1],
                      bBaseL + (p * 16 * BKH) * 2 + kb2);
            }

#pragma unroll
            for (int mi = 0; mi < 2; mi++)
#pragma unroll
                for (int ni = 0; ni < 10; ni++) {
                    mma16816h(acc[mi][ni], afh[mi], bfh[ni]);
                    mma16816h(acc[mi][ni], afh[mi], bfl[ni]);
                    mma16816h(acc[mi][ni], afl[mi], bfh[ni]);
                }
        }
        __syncthreads();
    }

#pragma unroll
    for (int mi = 0; mi < 2; mi++) {
#pragma unroll
        for (int ni = 0; ni < 10; ni++) {
            int r = bm + wm + (mi << 4) + (lane >> 2);
            int c = bn + wn + (ni << 3) + ((lane & 3) << 1);
            if (c < N) {
                float2 v0 = make_float2(acc[mi][ni][0], acc[mi][ni][1]);
                float2 v1 = make_float2(acc[mi][ni][2], acc[mi][ni][3]);
                *(float2*)(C + (size_t)r * ldc + c) = v0;
                *(float2*)(C + (size_t)(r + 8) * ldc + c) = v1;
            }
        }
    }
}

// ---------------- mask format detection ----------------
__global__ void k_maskdetect(const unsigned char* __restrict__ m, int* flag) {
    int t = blockIdx.x * blockDim.x + threadIdx.x;
    int any = 0;
    for (int i = t; i < 65536; i += 256 * 64)
        if ((i & 3) != 0 && m[i]) any = 1;
    if (any) atomicExch(flag, 1);
}

// ---------------- CSR build ----------------
__global__ void k_zero_counts(int* cnt, int* flag) {
    int i = blockIdx.x * blockDim.x + threadIdx.x;
    if (i < 2 * NN) cnt[i] = 0;
    if (i == 0) *flag = 0;
}

__global__ void k_hist(const int* __restrict__ es, const int* __restrict__ er, int* cnt) {
    int i = blockIdx.x * blockDim.x + threadIdx.x;
    if (i < EE) {
        atomicAdd(&cnt[es[EE + i]], 1);
    } else if (i < 2 * EE) {
        int j = i - EE;
        atomicAdd(&cnt[NN + er[EE + j]], 1);
    }
}

__global__ void k_scan(const int* __restrict__ cnt, int* __restrict__ off, int* __restrict__ cur) {
    int b = blockIdx.x;
    const int* c = cnt + b * NN;
    int* o = off + b * (NN + 1);
    int* u = cur + b * NN;
    __shared__ int ts[1024];
    int t = threadIdx.x;
    int loc[8];
    int s = 0;
#pragma unroll
    for (int i = 0; i < 8; i++) { loc[i] = s; s += c[t * 8 + i]; }
    ts[t] = s;
    __syncthreads();
    for (int d = 1; d < 1024; d <<= 1) {
        int v = (t >= d) ? ts[t - d] : 0;
        __syncthreads();
        ts[t] += v;
        __syncthreads();
    }
    int base = (t > 0) ? ts[t - 1] : 0;
#pragma unroll
    for (int i = 0; i < 8; i++) {
        int v = base + loc[i];
        o[t * 8 + i] = v;
        u[t * 8 + i] = v;
    }
    if (t == 1023) o[NN] = ts[1023];
}

__global__ void k_fill(const int* __restrict__ es, const int* __restrict__ er,
                       int* cur, int* __restrict__ srcS, int* __restrict__ srcR) {
    int i = blockIdx.x * blockDim.x + threadIdx.x;
    if (i < EE) {
        int d = es[EE + i];
        int p = atomicAdd(&cur[d], 1);
        srcS[p] = es[i];
    } else if (i < 2 * EE) {
        int j = i - EE;
        int d = er[EE + j];
        int p = atomicAdd(&cur[NN + d], 1);
        srcR[p] = er[j];
    }
}

// ---------------- combine (float4 gathers: 4 cols/thread, 4 edge slots) ----------------
// Y row = 150 float4; self at f4-offset 0, sim msgs at 50, rat msgs at 100.
__global__ void k_combine(const float* __restrict__ Y, const float* __restrict__ bias,
                          const int* __restrict__ offS, const int* __restrict__ srcS,
                          const int* __restrict__ offR, const int* __restrict__ srcR,
                          float* __restrict__ out, __half* __restrict__ outh,
                          __half* __restrict__ outl, int do_relu)
{
    __shared__ int s_src[256];
    __shared__ float4 s_part[4][50];
    const int n = blockIdx.x;
    const int t = threadIdx.x;
    const int eoff = t / 50;     // 0..3 valid when t < 200
    const int cg   = t - eoff * 50;
    const float4* Y4 = (const float4*)Y;

    float4 acc = make_float4(0.f, 0.f, 0.f, 0.f);

    // sim aggregation (f4 bank 50)
    {
        int s0 = offS[n], s1 = offS[n + 1];
        for (int base = s0; base < s1; base += 256) {
            int cnt = min(256, s1 - base);
            __syncthreads();
            if (t < cnt) s_src[t] = srcS[base + t];
            __syncthreads();
            if (t < 200) {
#pragma unroll 4
                for (int i = 0; i < cnt; i += 4) {
                    int e = i + eoff;
                    if (e < cnt) {
                        float4 v = Y4[(size_t)s_src[e] * 150 + 50 + cg];
                        acc.x += v.x; acc.y += v.y; acc.z += v.z; acc.w += v.w;
                    }
                }
            }
        }
    }
    // rat aggregation (f4 bank 100)
    {
        int s0 = offR[n], s1 = offR[n + 1];
        for (int base = s0; base < s1; base += 256) {
            int cnt = min(256, s1 - base);
            __syncthreads();
            if (t < cnt) s_src[t] = srcR[base + t];
            __syncthreads();
            if (t < 200) {
#pragma unroll 4
                for (int i = 0; i < cnt; i += 4) {
                    int e = i + eoff;
                    if (e < cnt) {
                        float4 v = Y4[(size_t)s_src[e] * 150 + 100 + cg];
                        acc.x += v.x; acc.y += v.y; acc.z += v.z; acc.w += v.w;
                    }
                }
            }
        }
    }

    __syncthreads();
    if (t < 200) s_part[eoff][cg] = acc;
    __syncthreads();

    if (t < 50) {
        float4 a0 = s_part[0][t], a1 = s_part[1][t], a2 = s_part[2][t], a3 = s_part[3][t];
        float4 self = Y4[(size_t)n * 150 + t];
        float4 b4 = ((const float4*)bias)[t];
        float4 r;
        r.x = a0.x + a1.x + a2.x + a3.x + self.x + b4.x;
        r.y = a0.y + a1.y + a2.y + a3.y + self.y + b4.y;
        r.z = a0.z + a1.z + a2.z + a3.z + self.z + b4.z;
        r.w = a0.w + a1.w + a2.w + a3.w + self.w + b4.w;
        if (do_relu) {
            r.x = fmaxf(r.x, 0.f); r.y = fmaxf(r.y, 0.f);
            r.z = fmaxf(r.z, 0.f); r.w = fmaxf(r.w, 0.f);
        }
        ((float4*)(out + (size_t)n * HH))[t] = r;
        __half hx, lx, hy, ly, hz, lz, hw, lw;
        split_h(r.x, hx, lx); split_h(r.y, hy, ly);
        split_h(r.z, hz, lz); split_h(r.w, hw, lw);
        __half2 h01; h01.x = hx; h01.y = hy;
        __half2 h23; h23.x = hz; h23.y = hw;
        __half2 l01; l01.x = lx; l01.y = ly;
        __half2 l23; l23.x = lz; l23.y = lw;
        *(__half2*)(outh + n * KP2 + 4 * t)     = h01;
        *(__half2*)(outh + n * KP2 + 4 * t + 2) = h23;
        *(__half2*)(outl + n * KP2 + 4 * t)     = l01;
        *(__half2*)(outl + n * KP2 + 4 * t + 2) = l23;
    }
}

// ---------------- decoder (fp32 float4 gathers) ----------------
__global__ void k_decode(const float* __restrict__ hq, const float* __restrict__ h,
                         const int* __restrict__ er, const void* __restrict__ maskp,
                         const int* __restrict__ fmt, float* __restrict__ out)
{
    int g = blockIdx.x * blockDim.x + threadIdx.x;
    int e = g >> 5;
    int lane = g & 31;
    if (e >= EE) return;
    int src = er[e];
    int dst = er[EE + e];
    const float4* a = (const float4*)(hq + (size_t)src * HH);
    const float4* b = (const float4*)(h + (size_t)dst * HH);
    float s = 0.f;
    {
        float4 va = a[lane], vb = b[lane];
        s = fmaf(va.x, vb.x, fmaf(va.y, vb.y, fmaf(va.z, vb.z, va.w * vb.w)));
    }
    if (lane < 18) {
        float4 va = a[lane + 32], vb = b[lane + 32];
        s += fmaf(va.x, vb.x, fmaf(va.y, vb.y, fmaf(va.z, vb.z, va.w * vb.w)));
    }
#pragma unroll
    for (int o = 16; o; o >>= 1) s += __shfl_xor_sync(0xffffffffu, s, o);
    if (lane == 0) {
        int mb;
        if (*fmt) mb = ((const unsigned char*)maskp)[e];
        else      mb = ((const int*)maskp)[e];
        out[e] = mb ? (s + 3.5f) : 0.f;
    }
}

// ---------------- launch ----------------
extern "C" void kernel_launch(void* const* d_in, const int* in_sizes, int n_in,
                              void* d_out, int out_size)
{
    // Resolve inputs by element count
    const float *x = 0, *w1s = 0, *w1m = 0, *w1r = 0, *b1 = 0;
    const float *w2s = 0, *w2m = 0, *w2r = 0, *b2 = 0, *Q = 0;
    const int *es = 0, *er = 0;
    const void* mask = 0;
    int nE = 0, nW1 = 0, nB = 0, nS = 0;
    for (int i = 0; i < n_in; i++) {
        int s = in_sizes[i];
        void* p = d_in[i];
        if (s == NN * NN) x = (const float*)p;
        else if (s == 2 * EE) { if (nE == 0) es = (const int*)p; else er = (const int*)p; nE++; }
        else if (s == EE) mask = p;
        else if (s == NN * HH) { if (nW1 == 0) w1s = (const float*)p; else if (nW1 == 1) w1m = (const float*)p; else w1r = (const float*)p; nW1++; }
        else if (s == HH) { if (nB == 0) b1 = (const float*)p; else b2 = (const float*)p; nB++; }
        else if (s == HH * HH) {
            if (nS == 0) w2s = (const float*)p;
            else if (nS == 1) w2m = (const float*)p;
            else if (nS == 2) w2r = (const float*)p;
            else Q = (const float*)p;
            nS++;
        }
    }
    float* out = (float*)d_out;

    float *Y, *h1, *h2, *hq;
    __half *Ah, *Bh, *h1h, *h1l, *h2h, *h2l, *B2h, *B2l, *Qh, *Ql;
    int *cnt, *off, *cur, *srcS, *srcR, *mfmt;
    cudaGetSymbolAddress((void**)&Ah,   g_Ah);
    cudaGetSymbolAddress((void**)&Bh,   g_Bh);
    cudaGetSymbolAddress((void**)&h1h,  g_h1h);
    cudaGetSymbolAddress((void**)&h1l,  g_h1l);
    cudaGetSymbolAddress((void**)&h2h,  g_h2h);
    cudaGetSymbolAddress((void**)&h2l,  g_h2l);
    cudaGetSymbolAddress((void**)&B2h,  g_B2h);
    cudaGetSymbolAddress((void**)&B2l,  g_B2l);
    cudaGetSymbolAddress((void**)&Qh,   g_Qh);
    cudaGetSymbolAddress((void**)&Ql,   g_Ql);
    cudaGetSymbolAddress((void**)&Y,    g_Y);
    cudaGetSymbolAddress((void**)&h1,   g_h1);
    cudaGetSymbolAddress((void**)&h2,   g_h2);
    cudaGetSymbolAddress((void**)&hq,   g_hq);
    cudaGetSymbolAddress((void**)&cnt,  g_cnt);
    cudaGetSymbolAddress((void**)&off,  g_off);
    cudaGetSymbolAddress((void**)&cur,  g_cur);
    cudaGetSymbolAddress((void**)&srcS, g_srcS);
    cudaGetSymbolAddress((void**)&srcR, g_srcR);
    cudaGetSymbolAddress((void**)&mfmt, g_maskfmt);

    cudaFuncSetAttribute(k_gemm_fp16, cudaFuncAttributeMaxDynamicSharedMemorySize, GEMM_FP16_SMEM);
    cudaFuncSetAttribute(k_gemm_sp,   cudaFuncAttributeMaxDynamicSharedMemorySize, GEMM_SP_SMEM);

    const int* offS = off;
    const int* offR = off + (NN + 1);

    // order: big GEMM at launch index 3 for ncu sampling
    k_convA<<<(size_t)NN * NN / 4 / 256, 256>>>(x, Ah);                       // 0
    k_convB<<<dim3(NN / 32, NPAD / 32), 256>>>(w1s, w1m, w1r, Bh);            // 1
    k_zero_counts<<<(2 * NN + 255) / 256, 256>>>(cnt, mfmt);                  // 2
    k_gemm_fp16<<<dim3(NPAD / 160, NN / 128), 256, GEMM_FP16_SMEM>>>(Ah, Bh, Y, NCAT, NN, NCAT); // 3
    k_maskdetect<<<64, 256>>>((const unsigned char*)mask, mfmt);
    k_hist<<<(2 * EE + 255) / 256, 256>>>(es, er, cnt);
    k_scan<<<2, 1024>>>(cnt, off, cur);
    k_fill<<<(2 * EE + 255) / 256, 256>>>(es, er, cur, srcS, srcR);
    k_combine<<<NN, 256>>>(Y, b1, offS, srcS, offR, srcR, h1, h1h, h1l, 1);

    // layer 2 via split fp16 GEMM (3-product, ~fp32 accurate; K padded to 256)
    k_convW2sp<<<NPAD, 256>>>(w2s, w2m, w2r, B2h, B2l);
    k_gemm_sp<<<dim3(NPAD / 160, NN / 128), 256, GEMM_SP_SMEM>>>(h1h, h1l, B2h, B2l, Y, NCAT, KP2, NCAT);
    k_combine<<<NN, 256>>>(Y, b2, offS, srcS, offR, srcR, h2, h2h, h2l, 0);

    // decoder: hq = h2 @ Q via split fp16 GEMM, then per-edge fp32 dot
    k_convQsp<<<320, 256>>>(Q, Qh, Ql);
    k_gemm_sp<<<dim3(2, NN / 128), 256, GEMM_SP_SMEM>>>(h2h, h2l, Qh, Ql, hq, HH, KP2, HH);
    k_decode<<<EE / 8, 256>>>(hq, h2, er, mask, mfmt, out);
}

// round 15
// speedup vs baseline: 1.0917x; 1.0751x over previous
#include <cuda_runtime.h>
#include <cuda_fp16.h>
#include <cstdint>

// Problem constants (fixed shapes)
#define NN   8192
#define EE   524288
#define HH   200
#define NCAT 600
#define NPAD 640
#define KP2  256      // layer-2 K padded (200 -> 256)

// ---------------- static scratch ----------------
__device__ __half g_Ah[(size_t)NN * NN];    // row-major fp16 of x
__device__ __half g_Bh[(size_t)NPAD * NN];  // W1^T fp16 [640][8192] (n-major)
__device__ __half g_h1h[NN * KP2];          // h1 fp16 hi, K-padded (pad cols stay 0)
__device__ __half g_h1l[NN * KP2];          // h1 fp16 lo
__device__ __half g_h2h[NN * KP2];
__device__ __half g_h2l[NN * KP2];
__device__ __half g_B2h[NPAD * KP2];        // W2cat^T fp16 hi [640][256]
__device__ __half g_B2l[NPAD * KP2];
__device__ __half g_Qh[320 * KP2];          // Q^T fp16 hi [320][256]
__device__ __half g_Ql[320 * KP2];
__device__ float g_Y[(size_t)NN * NCAT];
__device__ float g_h1[NN * HH];
__device__ float g_h2[NN * HH];
__device__ float g_hq[NN * HH];
__device__ int   g_cnt[2 * NN];
__device__ int   g_off[2 * (NN + 1)];
__device__ int   g_cur[2 * NN];
__device__ int   g_srcS[EE];
__device__ int   g_srcR[EE];
__device__ int   g_maskfmt;

__device__ __forceinline__ void split_h(float v, __half& hi, __half& lo) {
    hi = __float2half_rn(v);
    lo = __float2half_rn(v - __half2float(hi));
}

__device__ __forceinline__ uint32_t smem_u32(const void* p) {
    uint32_t a;
    asm("{ .reg .u64 t; cvta.to.shared.u64 t, %1; cvt.u32.u64 %0, t; }" : "=r"(a) : "l"(p));
    return a;
}
__device__ __forceinline__ void cp16(uint32_t dst, const void* src) {
    asm volatile("cp.async.cg.shared.global [%0], [%1], 16;" :: "r"(dst), "l"(src));
}
__device__ __forceinline__ void ldsm4(uint32_t& r0, uint32_t& r1, uint32_t& r2, uint32_t& r3,
                                      uint32_t addr) {
    asm volatile("ldmatrix.sync.aligned.m8n8.x4.shared.b16 {%0,%1,%2,%3}, [%4];"
                 : "=r"(r0), "=r"(r1), "=r"(r2), "=r"(r3) : "r"(addr));
}
__device__ __forceinline__ void mma16816h(float* d, const uint32_t* a, const uint32_t* b) {
    asm volatile(
        "mma.sync.aligned.m16n8k16.row.col.f32.f16.f16.f32 "
        "{%0,%1,%2,%3},{%4,%5,%6,%7},{%8,%9},{%0,%1,%2,%3};\n"
        : "+f"(d[0]), "+f"(d[1]), "+f"(d[2]), "+f"(d[3])
        : "r"(a[0]), "r"(a[1]), "r"(a[2]), "r"(a[3]), "r"(b[0]), "r"(b[1]));
}

// ---------------- converters ----------------
__global__ void k_convA(const float* __restrict__ x, __half* __restrict__ hi) {
    size_t base = ((size_t)blockIdx.x * blockDim.x + threadIdx.x) * 4;
    float4 v = *(const float4*)(x + base);
    __half2 p0; p0.x = __float2half_rn(v.x); p0.y = __float2half_rn(v.y);
    __half2 p1; p1.x = __float2half_rn(v.z); p1.y = __float2half_rn(v.w);
    *(__half2*)(hi + base)     = p0;
    *(__half2*)(hi + base + 2) = p1;
}

// W1^T fp16 with transpose: out[n][k] = w_sel[k][n%200], n in [0,640), zero-pad n>=600
__global__ void k_convB(const float* __restrict__ w0, const float* __restrict__ w1,
                        const float* __restrict__ w2, __half* __restrict__ bh) {
    __shared__ float t[32][33];
    int kt = blockIdx.x;
    int nt = blockIdx.y;
    int tx = threadIdx.x & 31, ty = threadIdx.x >> 5;
#pragma unroll
    for (int i = 0; i < 32; i += 8) {
        int k = kt * 32 + ty + i;
        int n = nt * 32 + tx;
        float v = 0.f;
        if (n < NCAT) {
            const float* w = (n < HH) ? w0 : ((n < 2 * HH) ? w1 : w2);
            v = w[(size_t)k * HH + (n % HH)];
        }
        t[ty + i][tx] = v;
    }
    __syncthreads();
#pragma unroll
    for (int i = 0; i < 32; i += 8) {
        int n = nt * 32 + ty + i;
        int k = kt * 32 + tx;
        bh[(size_t)n * NN + k] = __float2half_rn(t[tx][ty + i]);
    }
}

// W2cat^T fp16 hi/lo
__global__ void k_convW2sp(const float* __restrict__ w0, const float* __restrict__ w1,
                           const float* __restrict__ w2, __half* __restrict__ bh,
                           __half* __restrict__ bl) {
    int idx = blockIdx.x * blockDim.x + threadIdx.x;
    int n = idx >> 8, k = idx & 255;
    float v = 0.f;
    if (n < NCAT && k < HH) {
        const float* w = (n < HH) ? w0 : ((n < 2 * HH) ? w1 : w2);
        v = w[k * HH + (n % HH)];
    }
    __half hi, lo;
    split_h(v, hi, lo);
    bh[idx] = hi;
    bl[idx] = lo;
}

// Q^T fp16 hi/lo
__global__ void k_convQsp(const float* __restrict__ Q, __half* __restrict__ qh,
                          __half* __restrict__ ql) {
    int idx = blockIdx.x * blockDim.x + threadIdx.x;
    int n = idx >> 8, k = idx & 255;
    float v = (n < HH && k < HH) ? Q[k * HH + n] : 0.f;
    __half hi, lo;
    split_h(v, hi, lo);
    qh[idx] = hi;
    ql[idx] = lo;
}

// ---------------- fp16 GEMM (single product): tile 128x160, BK=64, ldmatrix ----------------
#define BKH 72   // 64 + 8 halves padding (LDSM conflict-free)
#define SSTRIDE (BKH * (128 + 160))       // halves per stage
#define GEMM_FP16_SMEM (2 * SSTRIDE * 2)  // bytes (2 stages)

__global__ void __launch_bounds__(256, 2) k_gemm_fp16(
    const __half* __restrict__ Ah, const __half* __restrict__ Bh,
    float* __restrict__ C, int N, int K, int ldc)
{
    extern __shared__ __align__(16) __half sm[];
    const int tid  = threadIdx.x;
    const int lane = tid & 31;
    const int wid  = tid >> 5;
    const int wm   = (wid >> 1) << 5;   // 0,32,64,96
    const int wn   = (wid & 1) * 80;    // 0,80
    const int bm   = blockIdx.y * 128;
    const int bn   = blockIdx.x * 160;

    float acc[2][10][4];
#pragma unroll
    for (int mi = 0; mi < 2; mi++)
#pragma unroll
        for (int ni = 0; ni < 10; ni++)
#pragma unroll
            for (int c = 0; c < 4; c++) acc[mi][ni][c] = 0.f;

    const int ktiles = K >> 6;

    auto sAh = [&](int s) -> __half* { return sm + (size_t)s * SSTRIDE; };
    auto sBh = [&](int s) -> __half* { return sm + (size_t)s * SSTRIDE + 128 * BKH; };

    auto issue_load = [&](int kt) {
        int s = kt & 1;
        int gk = kt << 6;
#pragma unroll
        for (int i = 0; i < 4; i++) {
            int idx = i * 256 + tid;
            int r = idx >> 3, seg = (idx & 7) << 3;
            cp16(smem_u32(sAh(s) + r * BKH + seg), Ah + (size_t)(bm + r) * K + gk + seg);
        }
#pragma unroll
        for (int i = 0; i < 5; i++) {
            int idx = i * 256 + tid;
            int r = idx >> 3, seg = (idx & 7) << 3;
            cp16(smem_u32(sBh(s) + r * BKH + seg), Bh + (size_t)(bn + r) * K + gk + seg);
        }
        asm volatile("cp.async.commit_group;");
    };

    const int aOff = (wm + (lane & 7) + ((lane >> 3) & 1) * 8) * BKH + (lane >> 4) * 8;
    const int bOff = (wn + (lane & 7) + (lane >> 4) * 8) * BKH + ((lane >> 3) & 1) * 8;

    issue_load(0);

    for (int kt = 0; kt < ktiles; kt++) {
        if (kt + 1 < ktiles) {
            issue_load(kt + 1);
            asm volatile("cp.async.wait_group 1;");
        } else {
            asm volatile("cp.async.wait_group 0;");
        }
        __syncthreads();

        const uint32_t aBase = smem_u32(sAh(kt & 1)) + aOff * 2;
        const uint32_t bBase = smem_u32(sBh(kt & 1)) + bOff * 2;

#pragma unroll
        for (int ks = 0; ks < 4; ks++) {
            const int kb2 = (ks << 4) * 2;
            uint32_t af[2][4];
            uint32_t bf[10][2];

#pragma unroll
            for (int mi = 0; mi < 2; mi++)
                ldsm4(af[mi][0], af[mi][1], af[mi][2], af[mi][3],
                      aBase + (mi * 16 * BKH) * 2 + kb2);
#pragma unroll
            for (int p = 0; p < 5; p++)
                ldsm4(bf[2 * p][0], bf[2 * p][1], bf[2 * p + 1][0], bf[2 * p + 1][1],
                      bBase + (p * 16 * BKH) * 2 + kb2);

#pragma unroll
            for (int mi = 0; mi < 2; mi++)
#pragma unroll
                for (int ni = 0; ni < 10; ni++)
                    mma16816h(acc[mi][ni], af[mi], bf[ni]);
        }
        __syncthreads();
    }

#pragma unroll
    for (int mi = 0; mi < 2; mi++) {
#pragma unroll
        for (int ni = 0; ni < 10; ni++) {
            int r = bm + wm + (mi << 4) + (lane >> 2);
            int c = bn + wn + (ni << 3) + ((lane & 3) << 1);
            if (c < N) {
                float2 v0 = make_float2(acc[mi][ni][0], acc[mi][ni][1]);
                float2 v1 = make_float2(acc[mi][ni][2], acc[mi][ni][3]);
                *(float2*)(C + (size_t)r * ldc + c) = v0;
                *(float2*)(C + (size_t)(r + 8) * ldc + c) = v1;
            }
        }
    }
}

// ---------------- fp16 split GEMM (3 products, ~fp32 accurate): tile 128x160, BK=64 ----------------
#define SSTRIDE2 (BKH * (2 * 128 + 2 * 160))
#define GEMM_SP_SMEM (2 * SSTRIDE2 * 2)   // 1 CTA/SM

__global__ void __launch_bounds__(256, 1) k_gemm_sp(
    const __half* __restrict__ Ah, const __half* __restrict__ Al,
    const __half* __restrict__ Bh, const __half* __restrict__ Bl,
    float* __restrict__ C, int N, int K, int ldc)
{
    extern __shared__ __align__(16) __half sm[];
    const int tid  = threadIdx.x;
    const int lane = tid & 31;
    const int wid  = tid >> 5;
    const int wm   = (wid >> 1) << 5;
    const int wn   = (wid & 1) * 80;
    const int bm   = blockIdx.y * 128;
    const int bn   = blockIdx.x * 160;

    float acc[2][10][4];
#pragma unroll
    for (int mi = 0; mi < 2; mi++)
#pragma unroll
        for (int ni = 0; ni < 10; ni++)
#pragma unroll
            for (int c = 0; c < 4; c++) acc[mi][ni][c] = 0.f;

    const int ktiles = K >> 6;

    auto sA = [&](int s, int a) -> __half* { return sm + (size_t)s * SSTRIDE2 + a * 128 * BKH; };
    auto sB = [&](int s, int a) -> __half* { return sm + (size_t)s * SSTRIDE2 + 2 * 128 * BKH + a * 160 * BKH; };

    auto issue_load = [&](int kt) {
        int s = kt & 1;
        int gk = kt << 6;
        const __half* gA[2] = {Ah, Al};
        const __half* gB[2] = {Bh, Bl};
#pragma unroll
        for (int a = 0; a < 2; a++) {
#pragma unroll
            for (int i = 0; i < 4; i++) {
                int idx = i * 256 + tid;
                int r = idx >> 3, seg = (idx & 7) << 3;
                cp16(smem_u32(sA(s, a) + r * BKH + seg), gA[a] + (size_t)(bm + r) * K + gk + seg);
            }
#pragma unroll
            for (int i = 0; i < 5; i++) {
                int idx = i * 256 + tid;
                int r = idx >> 3, seg = (idx & 7) << 3;
                cp16(smem_u32(sB(s, a) + r * BKH + seg), gB[a] + (size_t)(bn + r) * K + gk + seg);
            }
        }
        asm volatile("cp.async.commit_group;");
    };

    const int aOff = (wm + (lane & 7) + ((lane >> 3) & 1) * 8) * BKH + (lane >> 4) * 8;
    const int bOff = (wn + (lane & 7) + (lane >> 4) * 8) * BKH + ((lane >> 3) & 1) * 8;

    issue_load(0);

    for (int kt = 0; kt < ktiles; kt++) {
        if (kt + 1 < ktiles) {
            issue_load(kt + 1);
            asm volatile("cp.async.wait_group 1;");
        } else {
            asm volatile("cp.async.wait_group 0;");
        }
        __syncthreads();

        const uint32_t aBaseH = smem_u32(sA(kt & 1, 0)) + aOff * 2;
        const uint32_t aBaseL = smem_u32(sA(kt & 1, 1)) + aOff * 2;
        const uint32_t bBaseH = smem_u32(sB(kt & 1, 0)) + bOff * 2;
        const uint32_t bBaseL = smem_u32(sB(kt & 1, 1)) + bOff * 2;

#pragma unroll
        for (int ks = 0; ks < 4; ks++) {
            const int kb2 = (ks << 4) * 2;
            uint32_t afh[2][4], afl[2][4];
            uint32_t bfh[10][2], bfl[10][2];

#pragma unroll
            for (int mi = 0; mi < 2; mi++) {
                ldsm4(afh[mi][0], afh[mi][1], afh[mi][2], afh[mi][3],
                      aBaseH + (mi * 16 * BKH) * 2 + kb2);
                ldsm4(afl[mi][0], afl[mi][1], afl[mi][2], afl[mi][3],
                      aBaseL + (mi * 16 * BKH) * 2 + kb2);
            }
#pragma unroll
            for (int p = 0; p < 5; p++) {
                ldsm4(bfh[2 * p][0], bfh[2 * p][1], bfh[2 * p + 1][0], bfh[2 * p + 1][1],
                      bBaseH + (p * 16 * BKH) * 2 + kb2);
                ldsm4(bfl[2 * p][0], bfl[2 * p][1], bfl[2 * p + 1][0], bfl[2 * p + 1][1],
                      bBaseL + (p * 16 * BKH) * 2 + kb2);
            }

#pragma unroll
            for (int mi = 0; mi < 2; mi++)
#pragma unroll
                for (int ni = 0; ni < 10; ni++) {
                    mma16816h(acc[mi][ni], afh[mi], bfh[ni]);
                    mma16816h(acc[mi][ni], afh[mi], bfl[ni]);
                    mma16816h(acc[mi][ni], afl[mi], bfh[ni]);
                }
        }
        __syncthreads();
    }

#pragma unroll
    for (int mi = 0; mi < 2; mi++) {
#pragma unroll
        for (int ni = 0; ni < 10; ni++) {
            int r = bm + wm + (mi << 4) + (lane >> 2);
            int c = bn + wn + (ni << 3) + ((lane & 3) << 1);
            if (c < N) {
                float2 v0 = make_float2(acc[mi][ni][0], acc[mi][ni][1]);
                float2 v1 = make_float2(acc[mi][ni][2], acc[mi][ni][3]);
                *(float2*)(C + (size_t)r * ldc + c) = v0;
                *(float2*)(C + (size_t)(r + 8) * ldc + c) = v1;
            }
        }
    }
}

// ---------------- CSR build ----------------
__global__ void k_zero_counts(int* cnt, int* flag) {
    int i = blockIdx.x * blockDim.x + threadIdx.x;
    if (i < 2 * NN) cnt[i] = 0;
    if (i == 0) *flag = 0;
}

// hist + mask-format detection fused (flag reset happens in k_zero_counts, which
// precedes this kernel on the same stream)
__global__ void k_hist(const int* __restrict__ es, const int* __restrict__ er, int* cnt,
                       const unsigned char* __restrict__ m, int* flag) {
    int i = blockIdx.x * blockDim.x + threadIdx.x;
    if (i < EE) {
        atomicAdd(&cnt[es[EE + i]], 1);
    } else if (i < 2 * EE) {
        int j = i - EE;
        atomicAdd(&cnt[NN + er[EE + j]], 1);
    }
    if (i < 16384) {
        int any = 0;
#pragma unroll
        for (int k2 = i; k2 < 65536; k2 += 16384)
            if ((k2 & 3) != 0 && m[k2]) any = 1;
        if (any) atomicExch(flag, 1);
    }
}

__global__ void k_scan(const int* __restrict__ cnt, int* __restrict__ off, int* __restrict__ cur) {
    int b = blockIdx.x;
    const int* c = cnt + b * NN;
    int* o = off + b * (NN + 1);
    int* u = cur + b * NN;
    __shared__ int ts[1024];
    int t = threadIdx.x;
    int loc[8];
    int s = 0;
#pragma unroll
    for (int i = 0; i < 8; i++) { loc[i] = s; s += c[t * 8 + i]; }
    ts[t] = s;
    __syncthreads();
    for (int d = 1; d < 1024; d <<= 1) {
        int v = (t >= d) ? ts[t - d] : 0;
        __syncthreads();
        ts[t] += v;
        __syncthreads();
    }
    int base = (t > 0) ? ts[t - 1] : 0;
#pragma unroll
    for (int i = 0; i < 8; i++) {
        int v = base + loc[i];
        o[t * 8 + i] = v;
        u[t * 8 + i] = v;
    }
    if (t == 1023) o[NN] = ts[1023];
}

__global__ void k_fill(const int* __restrict__ es, const int* __restrict__ er,
                       int* cur, int* __restrict__ srcS, int* __restrict__ srcR) {
    int i = blockIdx.x * blockDim.x + threadIdx.x;
    if (i < EE) {
        int d = es[EE + i];
        int p = atomicAdd(&cur[d], 1);
        srcS[p] = es[i];
    } else if (i < 2 * EE) {
        int j = i - EE;
        int d = er[EE + j];
        int p = atomicAdd(&cur[NN + d], 1);
        srcR[p] = er[j];
    }
}

// ---------------- combine (fp32 gathers, MLP=8, fused fp16 hi/lo output) ----------------
__global__ void k_combine(const float* __restrict__ Y, const float* __restrict__ bias,
                          const int* __restrict__ offS, const int* __restrict__ srcS,
                          const int* __restrict__ offR, const int* __restrict__ srcR,
                          float* __restrict__ out, __half* __restrict__ outh,
                          __half* __restrict__ outl, int do_relu)
{
    __shared__ int s_src[256];
    const int n = blockIdx.x;
    const int t = threadIdx.x;

    float acc = 0.f;
    if (t < HH) acc = Y[(size_t)n * NCAT + t] + bias[t];

    {
        int s0 = offS[n], s1 = offS[n + 1];
        for (int base = s0; base < s1; base += 256) {
            int cnt = min(256, s1 - base);
            __syncthreads();
            if (t < cnt) s_src[t] = srcS[base + t];
            __syncthreads();
            if (t < HH) {
#pragma unroll 8
                for (int i = 0; i < cnt; i++)
                    acc += Y[(size_t)s_src[i] * NCAT + HH + t];
            }
        }
    }
    {
        int s0 = offR[n], s1 = offR[n + 1];
        for (int base = s0; base < s1; base += 256) {
            int cnt = min(256, s1 - base);
            __syncthreads();
            if (t < cnt) s_src[t] = srcR[base + t];
            __syncthreads();
            if (t < HH) {
#pragma unroll 8
                for (int i = 0; i < cnt; i++)
                    acc += Y[(size_t)s_src[i] * NCAT + 2 * HH + t];
            }
        }
    }
    if (t < HH) {
        if (do_relu) acc = fmaxf(acc, 0.f);
        out[(size_t)n * HH + t] = acc;
        __half hi, lo;
        split_h(acc, hi, lo);
        outh[n * KP2 + t] = hi;   // pad cols [200,256) remain zero (zero-initialized globals)
        outl[n * KP2 + t] = lo;
    }
}

// ---------------- decoder (fp32 float4 gathers) ----------------
__global__ void k_decode(const float* __restrict__ hq, const float* __restrict__ h,
                         const int* __restrict__ er, const void* __restrict__ maskp,
                         const int* __restrict__ fmt, float* __restrict__ out)
{
    int g = blockIdx.x * blockDim.x + threadIdx.x;
    int e = g >> 5;
    int lane = g & 31;
    if (e >= EE) return;
    int src = er[e];
    int dst = er[EE + e];
    const float4* a = (const float4*)(hq + (size_t)src * HH);
    const float4* b = (const float4*)(h + (size_t)dst * HH);
    float s = 0.f;
    {
        float4 va = a[lane], vb = b[lane];
        s = fmaf(va.x, vb.x, fmaf(va.y, vb.y, fmaf(va.z, vb.z, va.w * vb.w)));
    }
    if (lane < 18) {
        float4 va = a[lane + 32], vb = b[lane + 32];
        s += fmaf(va.x, vb.x, fmaf(va.y, vb.y, fmaf(va.z, vb.z, va.w * vb.w)));
    }
#pragma unroll
    for (int o = 16; o; o >>= 1) s += __shfl_xor_sync(0xffffffffu, s, o);
    if (lane == 0) {
        int mb;
        if (*fmt) mb = ((const unsigned char*)maskp)[e];
        else      mb = ((const int*)maskp)[e];
        out[e] = mb ? (s + 3.5f) : 0.f;
    }
}

// ---------------- launch ----------------
extern "C" void kernel_launch(void* const* d_in, const int* in_sizes, int n_in,
                              void* d_out, int out_size)
{
    // Resolve inputs by element count
    const float *x = 0, *w1s = 0, *w1m = 0, *w1r = 0, *b1 = 0;
    const float *w2s = 0, *w2m = 0, *w2r = 0, *b2 = 0, *Q = 0;
    const int *es = 0, *er = 0;
    const void* mask = 0;
    int nE = 0, nW1 = 0, nB = 0, nS = 0;
    for (int i = 0; i < n_in; i++) {
        int s = in_sizes[i];
        void* p = d_in[i];
        if (s == NN * NN) x = (const float*)p;
        else if (s == 2 * EE) { if (nE == 0) es = (const int*)p; else er = (const int*)p; nE++; }
        else if (s == EE) mask = p;
        else if (s == NN * HH) { if (nW1 == 0) w1s = (const float*)p; else if (nW1 == 1) w1m = (const float*)p; else w1r = (const float*)p; nW1++; }
        else if (s == HH) { if (nB == 0) b1 = (const float*)p; else b2 = (const float*)p; nB++; }
        else if (s == HH * HH) {
            if (nS == 0) w2s = (const float*)p;
            else if (nS == 1) w2m = (const float*)p;
            else if (nS == 2) w2r = (const float*)p;
            else Q = (const float*)p;
            nS++;
        }
    }
    float* out = (float*)d_out;

    float *Y, *h1, *h2, *hq;
    __half *Ah, *Bh, *h1h, *h1l, *h2h, *h2l, *B2h, *B2l, *Qh, *Ql;
    int *cnt, *off, *cur, *srcS, *srcR, *mfmt;
    cudaGetSymbolAddress((void**)&Ah,   g_Ah);
    cudaGetSymbolAddress((void**)&Bh,   g_Bh);
    cudaGetSymbolAddress((void**)&h1h,  g_h1h);
    cudaGetSymbolAddress((void**)&h1l,  g_h1l);
    cudaGetSymbolAddress((void**)&h2h,  g_h2h);
    cudaGetSymbolAddress((void**)&h2l,  g_h2l);
    cudaGetSymbolAddress((void**)&B2h,  g_B2h);
    cudaGetSymbolAddress((void**)&B2l,  g_B2l);
    cudaGetSymbolAddress((void**)&Qh,   g_Qh);
    cudaGetSymbolAddress((void**)&Ql,   g_Ql);
    cudaGetSymbolAddress((void**)&Y,    g_Y);
    cudaGetSymbolAddress((void**)&h1,   g_h1);
    cudaGetSymbolAddress((void**)&h2,   g_h2);
    cudaGetSymbolAddress((void**)&hq,   g_hq);
    cudaGetSymbolAddress((void**)&cnt,  g_cnt);
    cudaGetSymbolAddress((void**)&off,  g_off);
    cudaGetSymbolAddress((void**)&cur,  g_cur);
    cudaGetSymbolAddress((void**)&srcS, g_srcS);
    cudaGetSymbolAddress((void**)&srcR, g_srcR);
    cudaGetSymbolAddress((void**)&mfmt, g_maskfmt);

    cudaFuncSetAttribute(k_gemm_fp16, cudaFuncAttributeMaxDynamicSharedMemorySize, GEMM_FP16_SMEM);
    cudaFuncSetAttribute(k_gemm_sp,   cudaFuncAttributeMaxDynamicSharedMemorySize, GEMM_SP_SMEM);

    const int* offS = off;
    const int* offR = off + (NN + 1);

    // side stream + fork/join events (created per call; not destroyed during
    // capture — kernel_launch is only invoked a handful of times)
    cudaStream_t side;
    cudaStreamCreateWithFlags(&side, cudaStreamNonBlocking);
    cudaEvent_t evF, evJ;
    cudaEventCreateWithFlags(&evF, cudaEventDisableTiming);
    cudaEventCreateWithFlags(&evJ, cudaEventDisableTiming);

    // main: converters for GEMM1
    k_convA<<<(size_t)NN * NN / 4 / 256, 256>>>(x, Ah);                       // 0
    k_convB<<<dim3(NN / 32, NPAD / 32), 256>>>(w1s, w1m, w1r, Bh);            // 1

    // fork side stream (CSR build + small converters run under GEMM1)
    cudaEventRecord(evF, 0);
    cudaStreamWaitEvent(side, evF, 0);
    k_zero_counts<<<(2 * NN + 255) / 256, 256, 0, side>>>(cnt, mfmt);         // 2

    // main: big GEMM (launch index 3 for ncu sampling)
    k_gemm_fp16<<<dim3(NPAD / 160, NN / 128), 256, GEMM_FP16_SMEM>>>(Ah, Bh, Y, NCAT, NN, NCAT);

    // side: CSR + layer-2/Q weight conversion
    k_hist<<<(2 * EE + 255) / 256, 256, 0, side>>>(es, er, cnt,
                                                   (const unsigned char*)mask, mfmt);
    k_scan<<<2, 1024, 0, side>>>(cnt, off, cur);
    k_fill<<<(2 * EE + 255) / 256, 256, 0, side>>>(es, er, cur, srcS, srcR);
    k_convW2sp<<<NPAD, 256, 0, side>>>(w2s, w2m, w2r, B2h, B2l);
    k_convQsp<<<320, 256, 0, side>>>(Q, Qh, Ql);

    // join: everything below needs CSR / converted weights
    cudaEventRecord(evJ, side);
    cudaStreamWaitEvent(0, evJ, 0);

    k_combine<<<NN, 256>>>(Y, b1, offS, srcS, offR, srcR, h1, h1h, h1l, 1);

    // layer 2 via split fp16 GEMM (3-product, ~fp32 accurate; K padded to 256)
    k_gemm_sp<<<dim3(NPAD / 160, NN / 128), 256, GEMM_SP_SMEM>>>(h1h, h1l, B2h, B2l, Y, NCAT, KP2, NCAT);
    k_combine<<<NN, 256>>>(Y, b2, offS, srcS, offR, srcR, h2, h2h, h2l, 0);

    // decoder: hq = h2 @ Q via split fp16 GEMM, then per-edge fp32 dot
    k_gemm_sp<<<dim3(2, NN / 128), 256, GEMM_SP_SMEM>>>(h2h, h2l, Qh, Ql, hq, HH, KP2, HH);
    k_decode<<<EE / 8, 256>>>(hq, h2, er, mask, mfmt, out);
}

// round 16
// speedup vs baseline: 1.1618x; 1.0643x over previous
#include <cuda_runtime.h>
#include <cuda_fp16.h>
#include <cstdint>

// Problem constants (fixed shapes)
#define NN   8192
#define EE   524288
#define HH   200
#define NCAT 600
#define NPAD 640
#define KP2  256      // layer-2 K padded (200 -> 256)

// ---------------- static scratch ----------------
__device__ __half g_Ah[(size_t)NN * NN];    // row-major fp16 of x
__device__ __half g_Bh[(size_t)NPAD * NN];  // W1^T fp16 [640][8192] (n-major)
__device__ __half g_h1h[NN * KP2];          // h1 fp16 hi, K-padded (pad cols stay 0)
__device__ __half g_h1l[NN * KP2];          // h1 fp16 lo
__device__ __half g_h2h[NN * KP2];
__device__ __half g_h2l[NN * KP2];
__device__ __half g_B2h[NPAD * KP2];        // W2cat^T fp16 hi [640][256]
__device__ __half g_B2l[NPAD * KP2];
__device__ __half g_Qh[320 * KP2];          // Q^T fp16 hi [320][256]
__device__ __half g_Ql[320 * KP2];
__device__ float g_Y[(size_t)NN * NCAT];
__device__ float g_h1[NN * HH];
__device__ float g_h2[NN * HH];
__device__ float g_hq[NN * HH];
__device__ int   g_cnt[2 * NN];
__device__ int   g_off[2 * (NN + 1)];
__device__ int   g_cur[2 * NN];
__device__ int   g_srcS[EE];
__device__ int   g_srcR[EE];
__device__ int   g_eidR[EE];                // original edge id for rat CSR entries
__device__ int   g_maskfmt;

__device__ __forceinline__ void split_h(float v, __half& hi, __half& lo) {
    hi = __float2half_rn(v);
    lo = __float2half_rn(v - __half2float(hi));
}

__device__ __forceinline__ uint32_t smem_u32(const void* p) {
    uint32_t a;
    asm("{ .reg .u64 t; cvta.to.shared.u64 t, %1; cvt.u32.u64 %0, t; }" : "=r"(a) : "l"(p));
    return a;
}
__device__ __forceinline__ void cp16(uint32_t dst, const void* src) {
    asm volatile("cp.async.cg.shared.global [%0], [%1], 16;" :: "r"(dst), "l"(src));
}
__device__ __forceinline__ void ldsm4(uint32_t& r0, uint32_t& r1, uint32_t& r2, uint32_t& r3,
                                      uint32_t addr) {
    asm volatile("ldmatrix.sync.aligned.m8n8.x4.shared.b16 {%0,%1,%2,%3}, [%4];"
                 : "=r"(r0), "=r"(r1), "=r"(r2), "=r"(r3) : "r"(addr));
}
__device__ __forceinline__ void mma16816h(float* d, const uint32_t* a, const uint32_t* b) {
    asm volatile(
        "mma.sync.aligned.m16n8k16.row.col.f32.f16.f16.f32 "
        "{%0,%1,%2,%3},{%4,%5,%6,%7},{%8,%9},{%0,%1,%2,%3};\n"
        : "+f"(d[0]), "+f"(d[1]), "+f"(d[2]), "+f"(d[3])
        : "r"(a[0]), "r"(a[1]), "r"(a[2]), "r"(a[3]), "r"(b[0]), "r"(b[1]));
}

// ---------------- converters ----------------
__global__ void k_convA(const float* __restrict__ x, __half* __restrict__ hi) {
    size_t base = ((size_t)blockIdx.x * blockDim.x + threadIdx.x) * 4;
    float4 v = *(const float4*)(x + base);
    __half2 p0; p0.x = __float2half_rn(v.x); p0.y = __float2half_rn(v.y);
    __half2 p1; p1.x = __float2half_rn(v.z); p1.y = __float2half_rn(v.w);
    *(__half2*)(hi + base)     = p0;
    *(__half2*)(hi + base + 2) = p1;
}

// W1^T fp16 with transpose: out[n][k] = w_sel[k][n%200], n in [0,640), zero-pad n>=600
__global__ void k_convB(const float* __restrict__ w0, const float* __restrict__ w1,
                        const float* __restrict__ w2, __half* __restrict__ bh) {
    __shared__ float t[32][33];
    int kt = blockIdx.x;
    int nt = blockIdx.y;
    int tx = threadIdx.x & 31, ty = threadIdx.x >> 5;
#pragma unroll
    for (int i = 0; i < 32; i += 8) {
        int k = kt * 32 + ty + i;
        int n = nt * 32 + tx;
        float v = 0.f;
        if (n < NCAT) {
            const float* w = (n < HH) ? w0 : ((n < 2 * HH) ? w1 : w2);
            v = w[(size_t)k * HH + (n % HH)];
        }
        t[ty + i][tx] = v;
    }
    __syncthreads();
#pragma unroll
    for (int i = 0; i < 32; i += 8) {
        int n = nt * 32 + ty + i;
        int k = kt * 32 + tx;
        bh[(size_t)n * NN + k] = __float2half_rn(t[tx][ty + i]);
    }
}

// W2cat^T fp16 hi/lo
__global__ void k_convW2sp(const float* __restrict__ w0, const float* __restrict__ w1,
                           const float* __restrict__ w2, __half* __restrict__ bh,
                           __half* __restrict__ bl) {
    int idx = blockIdx.x * blockDim.x + threadIdx.x;
    int n = idx >> 8, k = idx & 255;
    float v = 0.f;
    if (n < NCAT && k < HH) {
        const float* w = (n < HH) ? w0 : ((n < 2 * HH) ? w1 : w2);
        v = w[k * HH + (n % HH)];
    }
    __half hi, lo;
    split_h(v, hi, lo);
    bh[idx] = hi;
    bl[idx] = lo;
}

// Q^T fp16 hi/lo
__global__ void k_convQsp(const float* __restrict__ Q, __half* __restrict__ qh,
                          __half* __restrict__ ql) {
    int idx = blockIdx.x * blockDim.x + threadIdx.x;
    int n = idx >> 8, k = idx & 255;
    float v = (n < HH && k < HH) ? Q[k * HH + n] : 0.f;
    __half hi, lo;
    split_h(v, hi, lo);
    qh[idx] = hi;
    ql[idx] = lo;
}

// ---------------- fp16 GEMM (single product): tile 128x160, BK=64, ldmatrix ----------------
#define BKH 72   // 64 + 8 halves padding (LDSM conflict-free)
#define SSTRIDE (BKH * (128 + 160))       // halves per stage
#define GEMM_FP16_SMEM (2 * SSTRIDE * 2)  // bytes (2 stages)

__global__ void __launch_bounds__(256, 2) k_gemm_fp16(
    const __half* __restrict__ Ah, const __half* __restrict__ Bh,
    float* __restrict__ C, int N, int K, int ldc)
{
    extern __shared__ __align__(16) __half sm[];
    const int tid  = threadIdx.x;
    const int lane = tid & 31;
    const int wid  = tid >> 5;
    const int wm   = (wid >> 1) << 5;   // 0,32,64,96
    const int wn   = (wid & 1) * 80;    // 0,80
    const int bm   = blockIdx.y * 128;
    const int bn   = blockIdx.x * 160;

    float acc[2][10][4];
#pragma unroll
    for (int mi = 0; mi < 2; mi++)
#pragma unroll
        for (int ni = 0; ni < 10; ni++)
#pragma unroll
            for (int c = 0; c < 4; c++) acc[mi][ni][c] = 0.f;

    const int ktiles = K >> 6;

    auto sAh = [&](int s) -> __half* { return sm + (size_t)s * SSTRIDE; };
    auto sBh = [&](int s) -> __half* { return sm + (size_t)s * SSTRIDE + 128 * BKH; };

    auto issue_load = [&](int kt) {
        int s = kt & 1;
        int gk = kt << 6;
#pragma unroll
        for (int i = 0; i < 4; i++) {
            int idx = i * 256 + tid;
            int r = idx >> 3, seg = (idx & 7) << 3;
            cp16(smem_u32(sAh(s) + r * BKH + seg), Ah + (size_t)(bm + r) * K + gk + seg);
        }
#pragma unroll
        for (int i = 0; i < 5; i++) {
            int idx = i * 256 + tid;
            int r = idx >> 3, seg = (idx & 7) << 3;
            cp16(smem_u32(sBh(s) + r * BKH + seg), Bh + (size_t)(bn + r) * K + gk + seg);
        }
        asm volatile("cp.async.commit_group;");
    };

    const int aOff = (wm + (lane & 7) + ((lane >> 3) & 1) * 8) * BKH + (lane >> 4) * 8;
    const int bOff = (wn + (lane & 7) + (lane >> 4) * 8) * BKH + ((lane >> 3) & 1) * 8;

    issue_load(0);

    for (int kt = 0; kt < ktiles; kt++) {
        if (kt + 1 < ktiles) {
            issue_load(kt + 1);
            asm volatile("cp.async.wait_group 1;");
        } else {
            asm volatile("cp.async.wait_group 0;");
        }
        __syncthreads();

        const uint32_t aBase = smem_u32(sAh(kt & 1)) + aOff * 2;
        const uint32_t bBase = smem_u32(sBh(kt & 1)) + bOff * 2;

#pragma unroll
        for (int ks = 0; ks < 4; ks++) {
            const int kb2 = (ks << 4) * 2;
            uint32_t af[2][4];
            uint32_t bf[10][2];

#pragma unroll
            for (int mi = 0; mi < 2; mi++)
                ldsm4(af[mi][0], af[mi][1], af[mi][2], af[mi][3],
                      aBase + (mi * 16 * BKH) * 2 + kb2);
#pragma unroll
            for (int p = 0; p < 5; p++)
                ldsm4(bf[2 * p][0], bf[2 * p][1], bf[2 * p + 1][0], bf[2 * p + 1][1],
                      bBase + (p * 16 * BKH) * 2 + kb2);

#pragma unroll
            for (int mi = 0; mi < 2; mi++)
#pragma unroll
                for (int ni = 0; ni < 10; ni++)
                    mma16816h(acc[mi][ni], af[mi], bf[ni]);
        }
        __syncthreads();
    }

#pragma unroll
    for (int mi = 0; mi < 2; mi++) {
#pragma unroll
        for (int ni = 0; ni < 10; ni++) {
            int r = bm + wm + (mi << 4) + (lane >> 2);
            int c = bn + wn + (ni << 3) + ((lane & 3) << 1);
            if (c < N) {
                float2 v0 = make_float2(acc[mi][ni][0], acc[mi][ni][1]);
                float2 v1 = make_float2(acc[mi][ni][2], acc[mi][ni][3]);
                *(float2*)(C + (size_t)r * ldc + c) = v0;
                *(float2*)(C + (size_t)(r + 8) * ldc + c) = v1;
            }
        }
    }
}

// ---------------- fp16 split GEMM (3 products, ~fp32 accurate): tile 128x160, BK=64 ----------------
#define SSTRIDE2 (BKH * (2 * 128 + 2 * 160))
#define GEMM_SP_SMEM (2 * SSTRIDE2 * 2)   // 1 CTA/SM

__global__ void __launch_bounds__(256, 1) k_gemm_sp(
    const __half* __restrict__ Ah, const __half* __restrict__ Al,
    const __half* __restrict__ Bh, const __half* __restrict__ Bl,
    float* __restrict__ C, int N, int K, int ldc)
{
    extern __shared__ __align__(16) __half sm[];
    const int tid  = threadIdx.x;
    const int lane = tid & 31;
    const int wid  = tid >> 5;
    const int wm   = (wid >> 1) << 5;
    const int wn   = (wid & 1) * 80;
    const int bm   = blockIdx.y * 128;
    const int bn   = blockIdx.x * 160;

    float acc[2][10][4];
#pragma unroll
    for (int mi = 0; mi < 2; mi++)
#pragma unroll
        for (int ni = 0; ni < 10; ni++)
#pragma unroll
            for (int c = 0; c < 4; c++) acc[mi][ni][c] = 0.f;

    const int ktiles = K >> 6;

    auto sA = [&](int s, int a) -> __half* { return sm + (size_t)s * SSTRIDE2 + a * 128 * BKH; };
    auto sB = [&](int s, int a) -> __half* { return sm + (size_t)s * SSTRIDE2 + 2 * 128 * BKH + a * 160 * BKH; };

    auto issue_load = [&](int kt) {
        int s = kt & 1;
        int gk = kt << 6;
        const __half* gA[2] = {Ah, Al};
        const __half* gB[2] = {Bh, Bl};
#pragma unroll
        for (int a = 0; a < 2; a++) {
#pragma unroll
            for (int i = 0; i < 4; i++) {
                int idx = i * 256 + tid;
                int r = idx >> 3, seg = (idx & 7) << 3;
                cp16(smem_u32(sA(s, a) + r * BKH + seg), gA[a] + (size_t)(bm + r) * K + gk + seg);
            }
#pragma unroll
            for (int i = 0; i < 5; i++) {
                int idx = i * 256 + tid;
                int r = idx >> 3, seg = (idx & 7) << 3;
                cp16(smem_u32(sB(s, a) + r * BKH + seg), gB[a] + (size_t)(bn + r) * K + gk + seg);
            }
        }
        asm volatile("cp.async.commit_group;");
    };

    const int aOff = (wm + (lane & 7) + ((lane >> 3) & 1) * 8) * BKH + (lane >> 4) * 8;
    const int bOff = (wn + (lane & 7) + (lane >> 4) * 8) * BKH + ((lane >> 3) & 1) * 8;

    issue_load(0);

    for (int kt = 0; kt < ktiles; kt++) {
        if (kt + 1 < ktiles) {
            issue_load(kt + 1);
            asm volatile("cp.async.wait_group 1;");
        } else {
            asm volatile("cp.async.wait_group 0;");
        }
        __syncthreads();

        const uint32_t aBaseH = smem_u32(sA(kt & 1, 0)) + aOff * 2;
        const uint32_t aBaseL = smem_u32(sA(kt & 1, 1)) + aOff * 2;
        const uint32_t bBaseH = smem_u32(sB(kt & 1, 0)) + bOff * 2;
        const uint32_t bBaseL = smem_u32(sB(kt & 1, 1)) + bOff * 2;

#pragma unroll
        for (int ks = 0; ks < 4; ks++) {
            const int kb2 = (ks << 4) * 2;
            uint32_t afh[2][4], afl[2][4];
            uint32_t bfh[10][2], bfl[10][2];

#pragma unroll
            for (int mi = 0; mi < 2; mi++) {
                ldsm4(afh[mi][0], afh[mi][1], afh[mi][2], afh[mi][3],
                      aBaseH + (mi * 16 * BKH) * 2 + kb2);
                ldsm4(afl[mi][0], afl[mi][1], afl[mi][2], afl[mi][3],
                      aBaseL + (mi * 16 * BKH) * 2 + kb2);
            }
#pragma unroll
            for (int p = 0; p < 5; p++) {
                ldsm4(bfh[2 * p][0], bfh[2 * p][1], bfh[2 * p + 1][0], bfh[2 * p + 1][1],
                      bBaseH + (p * 16 * BKH) * 2 + kb2);
                ldsm4(bfl[2 * p][0], bfl[2 * p][1], bfl[2 * p + 1][0], bfl[2 * p + 1][1],
                      bBaseL + (p * 16 * BKH) * 2 + kb2);
            }

#pragma unroll
            for (int mi = 0; mi < 2; mi++)
#pragma unroll
                for (int ni = 0; ni < 10; ni++) {
                    mma16816h(acc[mi][ni], afh[mi], bfh[ni]);
                    mma16816h(acc[mi][ni], afh[mi], bfl[ni]);
                    mma16816h(acc[mi][ni], afl[mi], bfh[ni]);
                }
        }
        __syncthreads();
    }

#pragma unroll
    for (int mi = 0; mi < 2; mi++) {
#pragma unroll
        for (int ni = 0; ni < 10; ni++) {
            int r = bm + wm + (mi << 4) + (lane >> 2);
            int c = bn + wn + (ni << 3) + ((lane & 3) << 1);
            if (c < N) {
                float2 v0 = make_float2(acc[mi][ni][0], acc[mi][ni][1]);
                float2 v1 = make_float2(acc[mi][ni][2], acc[mi][ni][3]);
                *(float2*)(C + (size_t)r * ldc + c) = v0;
                *(float2*)(C + (size_t)(r + 8) * ldc + c) = v1;
            }
        }
    }
}

// ---------------- CSR build ----------------
__global__ void k_zero_counts(int* cnt, int* flag) {
    int i = blockIdx.x * blockDim.x + threadIdx.x;
    if (i < 2 * NN) cnt[i] = 0;
    if (i == 0) *flag = 0;
}

// hist + mask-format detection fused
__global__ void k_hist(const int* __restrict__ es, const int* __restrict__ er, int* cnt,
                       const unsigned char* __restrict__ m, int* flag) {
    int i = blockIdx.x * blockDim.x + threadIdx.x;
    if (i < EE) {
        atomicAdd(&cnt[es[EE + i]], 1);
    } else if (i < 2 * EE) {
        int j = i - EE;
        atomicAdd(&cnt[NN + er[EE + j]], 1);
    }
    if (i < 16384) {
        int any = 0;
#pragma unroll
        for (int k2 = i; k2 < 65536; k2 += 16384)
            if ((k2 & 3) != 0 && m[k2]) any = 1;
        if (any) atomicExch(flag, 1);
    }
}

__global__ void k_scan(const int* __restrict__ cnt, int* __restrict__ off, int* __restrict__ cur) {
    int b = blockIdx.x;
    const int* c = cnt + b * NN;
    int* o = off + b * (NN + 1);
    int* u = cur + b * NN;
    __shared__ int ts[1024];
    int t = threadIdx.x;
    int loc[8];
    int s = 0;
#pragma unroll
    for (int i = 0; i < 8; i++) { loc[i] = s; s += c[t * 8 + i]; }
    ts[t] = s;
    __syncthreads();
    for (int d = 1; d < 1024; d <<= 1) {
        int v = (t >= d) ? ts[t - d] : 0;
        __syncthreads();
        ts[t] += v;
        __syncthreads();
    }
    int base = (t > 0) ? ts[t - 1] : 0;
#pragma unroll
    for (int i = 0; i < 8; i++) {
        int v = base + loc[i];
        o[t * 8 + i] = v;
        u[t * 8 + i] = v;
    }
    if (t == 1023) o[NN] = ts[1023];
}

__global__ void k_fill(const int* __restrict__ es, const int* __restrict__ er,
                       int* cur, int* __restrict__ srcS, int* __restrict__ srcR,
                       int* __restrict__ eidR) {
    int i = blockIdx.x * blockDim.x + threadIdx.x;
    if (i < EE) {
        int d = es[EE + i];
        int p = atomicAdd(&cur[d], 1);
        srcS[p] = es[i];
    } else if (i < 2 * EE) {
        int j = i - EE;
        int d = er[EE + j];
        int p = atomicAdd(&cur[NN + d], 1);
        srcR[p] = er[j];
        eidR[p] = j;
    }
}

// ---------------- combine (fp32 gathers, MLP=8, fused fp16 hi/lo output) ----------------
__global__ void k_combine(const float* __restrict__ Y, const float* __restrict__ bias,
                          const int* __restrict__ offS, const int* __restrict__ srcS,
                          const int* __restrict__ offR, const int* __restrict__ srcR,
                          float* __restrict__ out, __half* __restrict__ outh,
                          __half* __restrict__ outl, int do_relu)
{
    __shared__ int s_src[256];
    const int n = blockIdx.x;
    const int t = threadIdx.x;

    float acc = 0.f;
    if (t < HH) acc = Y[(size_t)n * NCAT + t] + bias[t];

    {
        int s0 = offS[n], s1 = offS[n + 1];
        for (int base = s0; base < s1; base += 256) {
            int cnt = min(256, s1 - base);
            __syncthreads();
            if (t < cnt) s_src[t] = srcS[base + t];
            __syncthreads();
            if (t < HH) {
#pragma unroll 8
                for (int i = 0; i < cnt; i++)
                    acc += Y[(size_t)s_src[i] * NCAT + HH + t];
            }
        }
    }
    {
        int s0 = offR[n], s1 = offR[n + 1];
        for (int base = s0; base < s1; base += 256) {
            int cnt = min(256, s1 - base);
            __syncthreads();
            if (t < cnt) s_src[t] = srcR[base + t];
            __syncthreads();
            if (t < HH) {
#pragma unroll 8
                for (int i = 0; i < cnt; i++)
                    acc += Y[(size_t)s_src[i] * NCAT + 2 * HH + t];
            }
        }
    }
    if (t < HH) {
        if (do_relu) acc = fmaxf(acc, 0.f);
        out[(size_t)n * HH + t] = acc;
        __half hi, lo;
        split_h(acc, hi, lo);
        outh[n * KP2 + t] = hi;   // pad cols [200,256) remain zero (zero-initialized globals)
        outl[n * KP2 + t] = lo;
    }
}

// ---------------- decoder (CSR-by-dst: h2 row staged in smem, hq gathered once/edge) ----------------
__global__ void k_decode_csr(const float* __restrict__ hq, const float* __restrict__ h,
                             const int* __restrict__ offR, const int* __restrict__ srcR,
                             const int* __restrict__ eidR, const void* __restrict__ maskp,
                             const int* __restrict__ fmt, float* __restrict__ out)
{
    __shared__ float4 s_h2[50];
    const int n = blockIdx.x;
    const int t = threadIdx.x;
    const int warp = t >> 5;
    const int lane = t & 31;

    if (t < 50) s_h2[t] = ((const float4*)(h + (size_t)n * HH))[t];
    __syncthreads();

    const int s0 = offR[n], s1 = offR[n + 1];
    const int mfm = *fmt;
    for (int idx = s0 + warp; idx < s1; idx += 8) {
        int src = srcR[idx];
        int eid = eidR[idx];
        const float4* a = (const float4*)(hq + (size_t)src * HH);
        float s = 0.f;
        {
            float4 va = a[lane], vb = s_h2[lane];
            s = fmaf(va.x, vb.x, fmaf(va.y, vb.y, fmaf(va.z, vb.z, va.w * vb.w)));
        }
        if (lane < 18) {
            float4 va = a[lane + 32], vb = s_h2[lane + 32];
            s += fmaf(va.x, vb.x, fmaf(va.y, vb.y, fmaf(va.z, vb.z, va.w * vb.w)));
        }
#pragma unroll
        for (int o = 16; o; o >>= 1) s += __shfl_xor_sync(0xffffffffu, s, o);
        if (lane == 0) {
            int mb;
            if (mfm) mb = ((const unsigned char*)maskp)[eid];
            else     mb = ((const int*)maskp)[eid];
            out[eid] = mb ? (s + 3.5f) : 0.f;
        }
    }
}

// ---------------- launch ----------------
extern "C" void kernel_launch(void* const* d_in, const int* in_sizes, int n_in,
                              void* d_out, int out_size)
{
    // Resolve inputs by element count
    const float *x = 0, *w1s = 0, *w1m = 0, *w1r = 0, *b1 = 0;
    const float *w2s = 0, *w2m = 0, *w2r = 0, *b2 = 0, *Q = 0;
    const int *es = 0, *er = 0;
    const void* mask = 0;
    int nE = 0, nW1 = 0, nB = 0, nS = 0;
    for (int i = 0; i < n_in; i++) {
        int s = in_sizes[i];
        void* p = d_in[i];
        if (s == NN * NN) x = (const float*)p;
        else if (s == 2 * EE) { if (nE == 0) es = (const int*)p; else er = (const int*)p; nE++; }
        else if (s == EE) mask = p;
        else if (s == NN * HH) { if (nW1 == 0) w1s = (const float*)p; else if (nW1 == 1) w1m = (const float*)p; else w1r = (const float*)p; nW1++; }
        else if (s == HH) { if (nB == 0) b1 = (const float*)p; else b2 = (const float*)p; nB++; }
        else if (s == HH * HH) {
            if (nS == 0) w2s = (const float*)p;
            else if (nS == 1) w2m = (const float*)p;
            else if (nS == 2) w2r = (const float*)p;
            else Q = (const float*)p;
            nS++;
        }
    }
    float* out = (float*)d_out;

    float *Y, *h1, *h2, *hq;
    __half *Ah, *Bh, *h1h, *h1l, *h2h, *h2l, *B2h, *B2l, *Qh, *Ql;
    int *cnt, *off, *cur, *srcS, *srcR, *eidR, *mfmt;
    cudaGetSymbolAddress((void**)&Ah,   g_Ah);
    cudaGetSymbolAddress((void**)&Bh,   g_Bh);
    cudaGetSymbolAddress((void**)&h1h,  g_h1h);
    cudaGetSymbolAddress((void**)&h1l,  g_h1l);
    cudaGetSymbolAddress((void**)&h2h,  g_h2h);
    cudaGetSymbolAddress((void**)&h2l,  g_h2l);
    cudaGetSymbolAddress((void**)&B2h,  g_B2h);
    cudaGetSymbolAddress((void**)&B2l,  g_B2l);
    cudaGetSymbolAddress((void**)&Qh,   g_Qh);
    cudaGetSymbolAddress((void**)&Ql,   g_Ql);
    cudaGetSymbolAddress((void**)&Y,    g_Y);
    cudaGetSymbolAddress((void**)&h1,   g_h1);
    cudaGetSymbolAddress((void**)&h2,   g_h2);
    cudaGetSymbolAddress((void**)&hq,   g_hq);
    cudaGetSymbolAddress((void**)&cnt,  g_cnt);
    cudaGetSymbolAddress((void**)&off,  g_off);
    cudaGetSymbolAddress((void**)&cur,  g_cur);
    cudaGetSymbolAddress((void**)&srcS, g_srcS);
    cudaGetSymbolAddress((void**)&srcR, g_srcR);
    cudaGetSymbolAddress((void**)&eidR, g_eidR);
    cudaGetSymbolAddress((void**)&mfmt, g_maskfmt);

    cudaFuncSetAttribute(k_gemm_fp16, cudaFuncAttributeMaxDynamicSharedMemorySize, GEMM_FP16_SMEM);
    cudaFuncSetAttribute(k_gemm_sp,   cudaFuncAttributeMaxDynamicSharedMemorySize, GEMM_SP_SMEM);

    const int* offS = off;
    const int* offR = off + (NN + 1);

    // side stream + fork/join events
    cudaStream_t side;
    cudaStreamCreateWithFlags(&side, cudaStreamNonBlocking);
    cudaEvent_t evF, evJ;
    cudaEventCreateWithFlags(&evF, cudaEventDisableTiming);
    cudaEventCreateWithFlags(&evJ, cudaEventDisableTiming);

    // main: converters for GEMM1
    k_convA<<<(size_t)NN * NN / 4 / 256, 256>>>(x, Ah);                       // 0
    k_convB<<<dim3(NN / 32, NPAD / 32), 256>>>(w1s, w1m, w1r, Bh);            // 1

    // fork side stream (CSR build + small converters run under GEMM1)
    cudaEventRecord(evF, 0);
    cudaStreamWaitEvent(side, evF, 0);
    k_zero_counts<<<(2 * NN + 255) / 256, 256, 0, side>>>(cnt, mfmt);         // 2

    // main: big GEMM (launch index 3 for ncu sampling)
    k_gemm_fp16<<<dim3(NPAD / 160, NN / 128), 256, GEMM_FP16_SMEM>>>(Ah, Bh, Y, NCAT, NN, NCAT);

    // side: CSR + layer-2/Q weight conversion
    k_hist<<<(2 * EE + 255) / 256, 256, 0, side>>>(es, er, cnt,
                                                   (const unsigned char*)mask, mfmt);
    k_scan<<<2, 1024, 0, side>>>(cnt, off, cur);
    k_fill<<<(2 * EE + 255) / 256, 256, 0, side>>>(es, er, cur, srcS, srcR, eidR);
    k_convW2sp<<<NPAD, 256, 0, side>>>(w2s, w2m, w2r, B2h, B2l);
    k_convQsp<<<320, 256, 0, side>>>(Q, Qh, Ql);

    // join
    cudaEventRecord(evJ, side);
    cudaStreamWaitEvent(0, evJ, 0);

    k_combine<<<NN, 256>>>(Y, b1, offS, srcS, offR, srcR, h1, h1h, h1l, 1);

    // layer 2 via split fp16 GEMM (3-product, ~fp32 accurate; K padded to 256)
    k_gemm_sp<<<dim3(NPAD / 160, NN / 128), 256, GEMM_SP_SMEM>>>(h1h, h1l, B2h, B2l, Y, NCAT, KP2, NCAT);
    k_combine<<<NN, 256>>>(Y, b2, offS, srcS, offR, srcR, h2, h2h, h2l, 0);

    // decoder: hq = h2 @ Q via split fp16 GEMM, then CSR-by-dst dot
    k_gemm_sp<<<dim3(2, NN / 128), 256, GEMM_SP_SMEM>>>(h2h, h2l, Qh, Ql, hq, HH, KP2, HH);
    k_decode_csr<<<NN, 256>>>(hq, h2, offR, srcR, eidR, mask, mfmt, out);
}